// round 8
// baseline (speedup 1.0000x reference)
#include <cuda_runtime.h>
#include <cuda_fp16.h>
#include <cstdint>
#include <cstddef>

// Problem constants: N=100000, E=1600000, F=128, H=64, C=40, G=2048
#define NMAX 100000
#define EMAX 1600000
#define GMAX 2048

// ---------------- scratch (device globals; no runtime alloc allowed) ----------------
__device__ __align__(128) float  g_h  [NMAX * 64];   // pre-MLP output (fp32)
__device__ __align__(128) __half g_hws[NMAX * 64];   // (h @ W) * isq (fp16) per layer
__device__ __align__(128) float  g_h1 [NMAX * 64];   // layer-1 activations (for skip)
__device__ __align__(16)  float  g_deg[NMAX];        // isq
__device__ __align__(128) float  g_readout[GMAX * 64];
__device__ __align__(16)  int    g_cnt[NMAX];        // per-dst degree
__device__ __align__(16)  int    g_ptr[NMAX];        // CSR row starts
__device__ __align__(16)  int    g_cursor[NMAX];     // fill cursors
__device__ __align__(16)  int    g_csr_src[EMAX];    // CSR column (src) indices
__device__ int g_scanflag[128];                      // lookback published aggregates (+1)
__device__ int g_idx32;                              // 1 if indices are int32

// ---------------- per-block index-dtype detection ----------------
__device__ __forceinline__ int block_detect_idx32(const void* e, int E, long long nlim,
                                                  int* s_flag) {
    if (threadIdx.x == 0) *s_flag = 0;
    __syncthreads();
    int m = E < 64 ? E : 64;
    if ((int)threadIdx.x < m) {
        long long v = ((const long long*)e)[threadIdx.x];
        if (v < 0 || v >= nlim) *s_flag = 1;
    }
    __syncthreads();
    return *s_flag;
}

// ---------------- degree histogram (4 edges/thread; block 0 publishes g_idx32) -------
__global__ void __launch_bounds__(256) k_hist(const void* __restrict__ eidx, int E,
                                              long long nlim) {
    __shared__ int sf;
    int idx32 = block_detect_idx32(eidx, E, nlim, &sf);
    if (blockIdx.x == 0 && threadIdx.x == 0) g_idx32 = idx32;
    int base = (blockIdx.x * blockDim.x + threadIdx.x) * 4;
    if (idx32) {
        const int* d = (const int*)eidx + E;
#pragma unroll
        for (int k = 0; k < 4; k++) {
            int e = base + k;
            if (e < E) atomicAdd(&g_cnt[d[e]], 1);
        }
    } else {
        const long long* d = (const long long*)eidx + E;
#pragma unroll
        for (int k = 0; k < 4; k++) {
            int e = base + k;
            if (e < E) atomicAdd(&g_cnt[(int)d[e]], 1);
        }
    }
}

// ---------------- single-pass exclusive scan (lookback) + cursor + isq ----------------
__global__ void __launch_bounds__(256) k_scan(int n) {
    __shared__ int wsum[8];
    __shared__ int red[8];
    __shared__ int s_prefix;
    int bid = blockIdx.x;
    int base = bid * 1024 + threadIdx.x * 4;

    int c0 = 0, c1 = 0, c2 = 0, c3 = 0;
    if (base + 3 < n) {
        int4 c = *(const int4*)&g_cnt[base];
        c0 = c.x; c1 = c.y; c2 = c.z; c3 = c.w;
    } else if (base < n) {
        c0 = g_cnt[base];
        if (base + 1 < n) c1 = g_cnt[base + 1];
        if (base + 2 < n) c2 = g_cnt[base + 2];
    }
    int tot = c0 + c1 + c2 + c3;
    int lane = threadIdx.x & 31, wid = threadIdx.x >> 5;
    int v = tot;
#pragma unroll
    for (int o = 1; o < 32; o <<= 1) {
        int u = __shfl_up_sync(0xffffffffu, v, o);
        if (lane >= o) v += u;
    }
    if (lane == 31) wsum[wid] = v;
    __syncthreads();
    if (threadIdx.x == 0) {
        int s = 0;
        for (int i = 0; i < 8; i++) { int t = wsum[i]; wsum[i] = s; s += t; }
        atomicExch(&g_scanflag[bid], s + 1);
    }
    __syncthreads();

    int part = 0;
    if ((int)threadIdx.x < bid) {
        volatile int* f = &g_scanflag[threadIdx.x];
        int x;
        do { x = *f; } while (x == 0);
        part = x - 1;
    }
#pragma unroll
    for (int o = 16; o; o >>= 1) part += __shfl_xor_sync(0xffffffffu, part, o);
    if (lane == 0) red[wid] = part;
    __syncthreads();
    if (threadIdx.x == 0) {
        int s = 0;
        for (int i = 0; i < 8; i++) s += red[i];
        s_prefix = s;
    }
    __syncthreads();

    int excl = v - tot + wsum[wid] + s_prefix;
    if (base < n) {
        int p0 = excl, p1 = p0 + c0, p2 = p1 + c1, p3 = p2 + c2;
        g_ptr[base] = p0; g_cursor[base] = p0; g_deg[base] = rsqrtf((float)c0 + 1.0f);
        if (base + 1 < n) { g_ptr[base+1] = p1; g_cursor[base+1] = p1; g_deg[base+1] = rsqrtf((float)c1 + 1.0f); }
        if (base + 2 < n) { g_ptr[base+2] = p2; g_cursor[base+2] = p2; g_deg[base+2] = rsqrtf((float)c2 + 1.0f); }
        if (base + 3 < n) { g_ptr[base+3] = p3; g_cursor[base+3] = p3; g_deg[base+3] = rsqrtf((float)c3 + 1.0f); }
    }
}

// ---------------- CSR fill (4 edges/thread, full grid) ----------------
__global__ void __launch_bounds__(256) k_fill(const void* __restrict__ eidx, int E,
                                              long long nlim) {
    __shared__ int sf;
    int idx32 = block_detect_idx32(eidx, E, nlim, &sf);
    int base = (blockIdx.x * blockDim.x + threadIdx.x) * 4;
#pragma unroll
    for (int k = 0; k < 4; k++) {
        int e = base + k;
        if (e >= E) break;
        int src, dst;
        if (idx32) {
            const int* p = (const int*)eidx;
            src = p[e]; dst = p[E + e];
        } else {
            const long long* p = (const long long*)eidx;
            src = (int)p[e]; dst = (int)p[E + e];
        }
        int pos = atomicAdd(&g_cursor[dst], 1);
        g_csr_src[pos] = src;
    }
}

// ---------------- row GEMM, packed f32x2 FMA; fp32+bias OR fp16*rsqrt(cnt+1) out -----
template<int K, int HALF_OUT>
__global__ void __launch_bounds__(128) k_gemm(const float* __restrict__ A,
                                              const float* __restrict__ W,
                                              const float* __restrict__ bias,
                                              const int* __restrict__ cnt,
                                              void* __restrict__ out, int n) {
    __shared__ ulonglong2 Ws[K * 16];
    __shared__ float      As[128 * 17];

    for (int i = threadIdx.x; i < K * 16; i += 128)
        Ws[i] = reinterpret_cast<const ulonglong2*>(W)[i];

    unsigned long long acc[32];
#pragma unroll
    for (int j = 0; j < 32; j++) acc[j] = 0ULL;

    int node = blockIdx.x * 128 + threadIdx.x;

    for (int k0 = 0; k0 < K; k0 += 16) {
        __syncthreads();
#pragma unroll
        for (int i = 0; i < 16; i++) {
            int idx = i * 128 + threadIdx.x;
            int nn = idx >> 4, kk = idx & 15;
            int gn = blockIdx.x * 128 + nn;
            As[nn * 17 + kk] = (gn < n) ? A[(size_t)gn * K + k0 + kk] : 0.f;
        }
        __syncthreads();
#pragma unroll
        for (int kk = 0; kk < 16; kk++) {
            float a = As[threadIdx.x * 17 + kk];
            unsigned long long a2;
            asm("mov.b64 %0, {%1, %1};" : "=l"(a2) : "f"(a));
            const ulonglong2* wr = &Ws[(k0 + kk) * 16];
#pragma unroll
            for (int j = 0; j < 16; j++) {
                ulonglong2 w = wr[j];
                asm("fma.rn.f32x2 %0, %1, %2, %0;" : "+l"(acc[2 * j])     : "l"(a2), "l"(w.x));
                asm("fma.rn.f32x2 %0, %1, %2, %0;" : "+l"(acc[2 * j + 1]) : "l"(a2), "l"(w.y));
            }
        }
    }

    if (node < n) {
        if (HALF_OUT) {
            float s = rsqrtf((float)__ldg(&cnt[node]) + 1.0f);
            __half2* o = reinterpret_cast<__half2*>(out) + (size_t)node * 32;
#pragma unroll
            for (int j = 0; j < 32; j++) {
                float lo, hi;
                asm("mov.b64 {%0, %1}, %2;" : "=f"(lo), "=f"(hi) : "l"(acc[j]));
                o[j] = __floats2half2_rn(lo * s, hi * s);
            }
        } else {
            float2* o = reinterpret_cast<float2*>(out) + (size_t)node * 32;
#pragma unroll
            for (int j = 0; j < 32; j++) {
                float lo, hi;
                asm("mov.b64 {%0, %1}, %2;" : "=f"(lo), "=f"(hi) : "l"(acc[j]));
                float2 b = reinterpret_cast<const float2*>(bias)[j];
                o[j] = make_float2(lo + b.x, hi + b.y);
            }
        }
    }
}

// ---------------- fused gather + self + bias + LN + ReLU (+skip+readout) -------------
// One warp per node, quarter-warp row vectorization: 8 lanes x uint4 (16B) per row,
// one LDG.128 covers 4 edges. Indices batch-loaded 32 at a time, shfl-distributed.
__global__ void __launch_bounds__(256) k_gather(const float* __restrict__ bias,
                                                const float* __restrict__ lng,
                                                const float* __restrict__ lnb,
                                                float* __restrict__ outh, int n,
                                                int do_readout,
                                                const void* __restrict__ batch) {
    const unsigned FULL = 0xffffffffu;
    int t = blockIdx.x * blockDim.x + threadIdx.x;
    int node = t >> 5, lane = t & 31;
    if (node >= n) return;
    int grp = lane >> 3, sub = lane & 7;

    int start = g_ptr[node];
    int cnt   = g_cnt[node];
    const uint4* hw4 = (const uint4*)g_hws;   // 8 x uint4 per 64-half row

    __half2 a0[4], a1[4];
    __half2 z = __float2half2_rn(0.f);
#pragma unroll
    for (int k = 0; k < 4; k++) { a0[k] = z; a1[k] = z; }

    int done = 0;
    while (done < cnt) {
        int m = cnt - done;
        if (m > 32) m = 32;
        int bidx = 0;
        if (lane < m) bidx = __ldg(&g_csr_src[start + done + lane]);

        int j = 0;
        for (; j + 8 <= m; j += 8) {
            int sA = __shfl_sync(FULL, bidx, j + grp);
            int sB = __shfl_sync(FULL, bidx, j + 4 + grp);
            uint4 vA = __ldg(&hw4[(size_t)sA * 8 + sub]);
            uint4 vB = __ldg(&hw4[(size_t)sB * 8 + sub]);
            const __half2* pA = (const __half2*)&vA;
            const __half2* pB = (const __half2*)&vB;
#pragma unroll
            for (int k = 0; k < 4; k++) {
                a0[k] = __hadd2(a0[k], pA[k]);
                a1[k] = __hadd2(a1[k], pB[k]);
            }
        }
        for (; j < m; j += 4) {
            int r = m - j;                       // 1..4 remaining
            int sel = j + (grp < r ? grp : 0);
            int sA = __shfl_sync(FULL, bidx, sel);
            if (grp < r) {
                uint4 vA = __ldg(&hw4[(size_t)sA * 8 + sub]);
                const __half2* pA = (const __half2*)&vA;
#pragma unroll
                for (int k = 0; k < 4; k++) a0[k] = __hadd2(a0[k], pA[k]);
            }
        }
        done += m;
    }

    // combine unroll accumulators + reduce across the 4 groups (xor 8, 16)
#pragma unroll
    for (int k = 0; k < 4; k++) {
        a0[k] = __hadd2(a0[k], a1[k]);
        a0[k] = __hadd2(a0[k], __shfl_xor_sync(FULL, a0[k], 8));
        a0[k] = __hadd2(a0[k], __shfl_xor_sync(FULL, a0[k], 16));
    }

    // self term + bias, fp32 (each lane owns halves [sub*8, sub*8+8))
    uint4 sv = __ldg(&hw4[(size_t)node * 8 + sub]);
    const __half2* ps = (const __half2*)&sv;
    float isqn = g_deg[node];
    const float4* b4 = (const float4*)bias;
    float4 bl = __ldg(&b4[sub * 2]), bh = __ldg(&b4[sub * 2 + 1]);
    float bb[8] = {bl.x, bl.y, bl.z, bl.w, bh.x, bh.y, bh.z, bh.w};

    float v[8];
#pragma unroll
    for (int k = 0; k < 4; k++) {
        float2 f  = __half22float2(a0[k]);
        float2 fs = __half22float2(ps[k]);
        v[2 * k]     = fmaf(isqn, f.x + fs.x, bb[2 * k]);
        v[2 * k + 1] = fmaf(isqn, f.y + fs.y, bb[2 * k + 1]);
    }

    // LayerNorm over 64 = 8 values/lane x 8 lanes/group (groups hold replicas)
    float sum = 0.f;
#pragma unroll
    for (int i = 0; i < 8; i++) sum += v[i];
#pragma unroll
    for (int o = 4; o; o >>= 1) sum += __shfl_xor_sync(FULL, sum, o);
    float mu = sum * (1.0f / 64.0f);

    float var = 0.f;
    float d[8];
#pragma unroll
    for (int i = 0; i < 8; i++) { d[i] = v[i] - mu; var += d[i] * d[i]; }
#pragma unroll
    for (int o = 4; o; o >>= 1) var += __shfl_xor_sync(FULL, var, o);
    float rstd = rsqrtf(var * (1.0f / 64.0f) + 1e-5f);

    const float4* g4 = (const float4*)lng;
    const float4* l4 = (const float4*)lnb;
    float4 gl = __ldg(&g4[sub * 2]), gh = __ldg(&g4[sub * 2 + 1]);
    float4 ll = __ldg(&l4[sub * 2]), lh = __ldg(&l4[sub * 2 + 1]);
    float gg[8] = {gl.x, gl.y, gl.z, gl.w, gh.x, gh.y, gh.z, gh.w};
    float lb[8] = {ll.x, ll.y, ll.z, ll.w, lh.x, lh.y, lh.z, lh.w};

    float o8[8];
#pragma unroll
    for (int i = 0; i < 8; i++)
        o8[i] = fmaxf(fmaf(d[i] * rstd, gg[i], lb[i]), 0.f);

    if (grp == 0) {
        if (!do_readout) {
            float4* o4 = (float4*)(outh + (size_t)node * 64 + sub * 8);
            o4[0] = make_float4(o8[0], o8[1], o8[2], o8[3]);
            o4[1] = make_float4(o8[4], o8[5], o8[6], o8[7]);
        } else {
            const float4* h14 = (const float4*)(g_h1 + (size_t)node * 64 + sub * 8);
            float4 ha = __ldg(&h14[0]), hb = __ldg(&h14[1]);
            int grpi = g_idx32 ? ((const int*)batch)[node]
                               : (int)((const long long*)batch)[node];
            float4* r4 = (float4*)(g_readout + (size_t)grpi * 64 + sub * 8);
            atomicAdd(&r4[0], make_float4(o8[0] + ha.x, o8[1] + ha.y, o8[2] + ha.z, o8[3] + ha.w));
            atomicAdd(&r4[1], make_float4(o8[4] + hb.x, o8[5] + hb.y, o8[6] + hb.z, o8[7] + hb.w));
        }
    }
}

// ---------------- post GEMM ----------------
__global__ void k_post(const float* __restrict__ W, const float* __restrict__ b,
                       float* __restrict__ out, int G) {
    __shared__ float r[64];
    int g = blockIdx.x;
    r[threadIdx.x] = g_readout[(size_t)g * 64 + threadIdx.x];
    __syncthreads();
    int c = threadIdx.x;
    if (c < 40) {
        float acc = b[c];
#pragma unroll
        for (int k = 0; k < 64; k++) acc = fmaf(r[k], __ldg(&W[k * 40 + c]), acc);
        out[(size_t)g * 40 + c] = acc;
    }
}

// ---------------- launch: hist(1) scan(2) fill(3) pregemm(4) gemm1(5) ... ------------
extern "C" void kernel_launch(void* const* d_in, const int* in_sizes, int n_in,
                              void* d_out, int out_size) {
    const float* x      = (const float*)d_in[0];
    const void*  eidx   = d_in[1];
    const void*  batch  = d_in[2];
    const float* pre_w  = (const float*)d_in[3];
    const float* pre_b  = (const float*)d_in[4];
    const float* c1_w   = (const float*)d_in[5];
    const float* c1_b   = (const float*)d_in[6];
    const float* n1_g   = (const float*)d_in[7];
    const float* n1_b   = (const float*)d_in[8];
    const float* c2_w   = (const float*)d_in[9];
    const float* c2_b   = (const float*)d_in[10];
    const float* n2_g   = (const float*)d_in[11];
    const float* n2_b   = (const float*)d_in[12];
    const float* post_w = (const float*)d_in[13];
    const float* post_b = (const float*)d_in[14];

    int N = in_sizes[0] / 128;
    int E = in_sizes[1] / 2;
    int G = out_size / 40;

    float *p_h, *p_h1, *p_readout;
    __half* p_hws;
    int *p_cnt, *p_flag;
    cudaGetSymbolAddress((void**)&p_h,       g_h);
    cudaGetSymbolAddress((void**)&p_hws,     g_hws);
    cudaGetSymbolAddress((void**)&p_h1,      g_h1);
    cudaGetSymbolAddress((void**)&p_cnt,     g_cnt);
    cudaGetSymbolAddress((void**)&p_flag,    g_scanflag);
    cudaGetSymbolAddress((void**)&p_readout, g_readout);

    static cudaStream_t s1 = nullptr, s2 = nullptr;
    static cudaEvent_t evFork = nullptr, evHist = nullptr, evG1 = nullptr, evCsr = nullptr;
    if (!s1) {
        cudaStreamCreateWithFlags(&s1, cudaStreamNonBlocking);
        cudaStreamCreateWithFlags(&s2, cudaStreamNonBlocking);
        cudaEventCreateWithFlags(&evFork, cudaEventDisableTiming);
        cudaEventCreateWithFlags(&evHist, cudaEventDisableTiming);
        cudaEventCreateWithFlags(&evG1,   cudaEventDisableTiming);
        cudaEventCreateWithFlags(&evCsr,  cudaEventDisableTiming);
    }

    cudaEventRecord(evFork, 0);
    cudaStreamWaitEvent(s1, evFork, 0);
    cudaStreamWaitEvent(s2, evFork, 0);

    // --- s2: memsets + CSR build (kernels #1-#3) ---
    cudaMemsetAsync(p_cnt, 0, (size_t)N * 4, s2);
    cudaMemsetAsync(p_flag, 0, 128 * 4, s2);
    cudaMemsetAsync(p_readout, 0, (size_t)G * 64 * 4, s2);
    k_hist<<<(E + 1023) / 1024, 256, 0, s2>>>(eidx, E, (long long)N);
    cudaEventRecord(evHist, s2);
    k_scan<<<(N + 1023) / 1024, 256, 0, s2>>>(N);
    k_fill<<<(E + 1023) / 1024, 256, 0, s2>>>(eidx, E, (long long)N);
    cudaEventRecord(evCsr, s2);

    // --- s1: pre-GEMM (#4, ncu target), gemm1 (#5, needs only hist counts) ---
    k_gemm<128, 0><<<(N + 127) / 128, 128, 0, s1>>>(x, pre_w, pre_b, nullptr, p_h, N);
    cudaStreamWaitEvent(s1, evHist, 0);
    k_gemm<64, 1><<<(N + 127) / 128, 128, 0, s1>>>(p_h, c1_w, nullptr, p_cnt, p_hws, N);
    cudaEventRecord(evG1, s1);

    // --- join on origin stream ---
    cudaStreamWaitEvent(0, evG1, 0);
    cudaStreamWaitEvent(0, evCsr, 0);

    // layer 1 gather -> h1 (#6)
    k_gather<<<((size_t)N * 32 + 255) / 256, 256>>>(c1_b, n1_g, n1_b, p_h1, N, 0, nullptr);

    // layer 2 (#7, #8)
    k_gemm<64, 1><<<(N + 127) / 128, 128>>>(p_h1, c2_w, nullptr, p_cnt, p_hws, N);
    k_gather<<<((size_t)N * 32 + 255) / 256, 256>>>(c2_b, n2_g, n2_b, nullptr, N, 1, batch);

    // post (#9)
    k_post<<<G, 64>>>(post_w, post_b, (float*)d_out, G);
}

// round 9
// speedup vs baseline: 1.1333x; 1.1333x over previous
#include <cuda_runtime.h>
#include <cuda_fp16.h>
#include <cstdint>
#include <cstddef>

// Problem constants: N=100000, E=1600000, F=128, H=64, C=40, G=2048
#define NMAX 100000
#define EMAX 1600000
#define GMAX 2048

// ---------------- scratch (device globals; no runtime alloc allowed) ----------------
__device__ __align__(128) float  g_h  [NMAX * 64];   // pre-MLP output (fp32)
__device__ __align__(128) __half g_hws[NMAX * 64];   // (h @ W) * isq (fp16) per layer
__device__ __align__(128) float  g_h1 [NMAX * 64];   // layer-1 activations (for skip)
__device__ __align__(16)  float  g_deg[NMAX];        // isq
__device__ __align__(128) float  g_readout[GMAX * 64];
__device__ __align__(16)  int    g_cnt[NMAX];        // per-dst degree
__device__ __align__(16)  int    g_ptr[NMAX];        // CSR row starts
__device__ __align__(16)  int    g_cursor[NMAX];     // fill cursors
__device__ __align__(16)  int    g_csr_src[EMAX];    // CSR column (src) indices
__device__ int g_scanflag[128];                      // lookback published aggregates (+1)
__device__ int g_idx32;                              // 1 if indices are int32

// ---------------- per-block index-dtype detection ----------------
__device__ __forceinline__ int block_detect_idx32(const void* e, int E, long long nlim,
                                                  int* s_flag) {
    if (threadIdx.x == 0) *s_flag = 0;
    __syncthreads();
    int m = E < 64 ? E : 64;
    if ((int)threadIdx.x < m) {
        long long v = ((const long long*)e)[threadIdx.x];
        if (v < 0 || v >= nlim) *s_flag = 1;
    }
    __syncthreads();
    return *s_flag;
}

// ---------------- degree histogram (4 edges/thread; block 0 publishes g_idx32) -------
__global__ void __launch_bounds__(256) k_hist(const void* __restrict__ eidx, int E,
                                              long long nlim) {
    __shared__ int sf;
    int idx32 = block_detect_idx32(eidx, E, nlim, &sf);
    if (blockIdx.x == 0 && threadIdx.x == 0) g_idx32 = idx32;
    int base = (blockIdx.x * blockDim.x + threadIdx.x) * 4;
    if (idx32) {
        const int* d = (const int*)eidx + E;
#pragma unroll
        for (int k = 0; k < 4; k++) {
            int e = base + k;
            if (e < E) atomicAdd(&g_cnt[d[e]], 1);
        }
    } else {
        const long long* d = (const long long*)eidx + E;
#pragma unroll
        for (int k = 0; k < 4; k++) {
            int e = base + k;
            if (e < E) atomicAdd(&g_cnt[(int)d[e]], 1);
        }
    }
}

// ---------------- single-pass exclusive scan (lookback) + cursor + isq ----------------
__global__ void __launch_bounds__(256) k_scan(int n) {
    __shared__ int wsum[8];
    __shared__ int red[8];
    __shared__ int s_prefix;
    int bid = blockIdx.x;
    int base = bid * 1024 + threadIdx.x * 4;

    int c0 = 0, c1 = 0, c2 = 0, c3 = 0;
    if (base + 3 < n) {
        int4 c = *(const int4*)&g_cnt[base];
        c0 = c.x; c1 = c.y; c2 = c.z; c3 = c.w;
    } else if (base < n) {
        c0 = g_cnt[base];
        if (base + 1 < n) c1 = g_cnt[base + 1];
        if (base + 2 < n) c2 = g_cnt[base + 2];
    }
    int tot = c0 + c1 + c2 + c3;
    int lane = threadIdx.x & 31, wid = threadIdx.x >> 5;
    int v = tot;
#pragma unroll
    for (int o = 1; o < 32; o <<= 1) {
        int u = __shfl_up_sync(0xffffffffu, v, o);
        if (lane >= o) v += u;
    }
    if (lane == 31) wsum[wid] = v;
    __syncthreads();
    if (threadIdx.x == 0) {
        int s = 0;
        for (int i = 0; i < 8; i++) { int t = wsum[i]; wsum[i] = s; s += t; }
        atomicExch(&g_scanflag[bid], s + 1);
    }
    __syncthreads();

    int part = 0;
    if ((int)threadIdx.x < bid) {
        volatile int* f = &g_scanflag[threadIdx.x];
        int x;
        do { x = *f; } while (x == 0);
        part = x - 1;
    }
#pragma unroll
    for (int o = 16; o; o >>= 1) part += __shfl_xor_sync(0xffffffffu, part, o);
    if (lane == 0) red[wid] = part;
    __syncthreads();
    if (threadIdx.x == 0) {
        int s = 0;
        for (int i = 0; i < 8; i++) s += red[i];
        s_prefix = s;
    }
    __syncthreads();

    int excl = v - tot + wsum[wid] + s_prefix;
    if (base < n) {
        int p0 = excl, p1 = p0 + c0, p2 = p1 + c1, p3 = p2 + c2;
        g_ptr[base] = p0; g_cursor[base] = p0; g_deg[base] = rsqrtf((float)c0 + 1.0f);
        if (base + 1 < n) { g_ptr[base+1] = p1; g_cursor[base+1] = p1; g_deg[base+1] = rsqrtf((float)c1 + 1.0f); }
        if (base + 2 < n) { g_ptr[base+2] = p2; g_cursor[base+2] = p2; g_deg[base+2] = rsqrtf((float)c2 + 1.0f); }
        if (base + 3 < n) { g_ptr[base+3] = p3; g_cursor[base+3] = p3; g_deg[base+3] = rsqrtf((float)c3 + 1.0f); }
    }
}

// ---------------- CSR fill (4 edges/thread, full grid) ----------------
__global__ void __launch_bounds__(256) k_fill(const void* __restrict__ eidx, int E,
                                              long long nlim) {
    __shared__ int sf;
    int idx32 = block_detect_idx32(eidx, E, nlim, &sf);
    int base = (blockIdx.x * blockDim.x + threadIdx.x) * 4;
#pragma unroll
    for (int k = 0; k < 4; k++) {
        int e = base + k;
        if (e >= E) break;
        int src, dst;
        if (idx32) {
            const int* p = (const int*)eidx;
            src = p[e]; dst = p[E + e];
        } else {
            const long long* p = (const long long*)eidx;
            src = (int)p[e]; dst = (int)p[E + e];
        }
        int pos = atomicAdd(&g_cursor[dst], 1);
        g_csr_src[pos] = src;
    }
}

// ---------------- register-blocked GEMM: 4 nodes x 16 cols per thread ----------------
// out[n,64] = A[n,K] @ W[K,64]; per k-step: 1 LDS.128 (A, transposed tile) +
// 4 LDS.128 (W, pre-packed f32x2) + 32 FFMA2. 256 thr = 64 nodegrps x 4 colgrps,
// 256 nodes per block.
template<int K, int HALF_OUT>
__global__ void __launch_bounds__(256, 2) k_gemm(const float* __restrict__ A,
                                                 const float* __restrict__ W,
                                                 const float* __restrict__ bias,
                                                 const int* __restrict__ cnt,
                                                 void* __restrict__ out, int n) {
    __shared__ ulonglong2 Ws[K * 16];      // K rows x 64 floats as packed f32x2 quads
    __shared__ float      As[16 * 256];    // As[kk][node], stride 256 (conflict-free)

    int tid = threadIdx.x;
    for (int i = tid; i < K * 16; i += 256)
        Ws[i] = reinterpret_cast<const ulonglong2*>(W)[i];

    int colgrp  = tid & 3;          // 16 cols: colgrp*16 ..
    int nodegrp = tid >> 2;         // 4 nodes: nodegrp*4 ..
    int nodeBase = blockIdx.x * 256;

    unsigned long long acc[32];     // [node i][pair p] -> acc[i*8+p]
#pragma unroll
    for (int j = 0; j < 32; j++) acc[j] = 0ULL;

    int myrow = nodeBase + tid;     // staging: thread t owns node t of the tile
    bool rowok = (myrow < n);

    for (int k0 = 0; k0 < K; k0 += 16) {
        __syncthreads();
        // stage A tile transposed: As[kk][t] = A[myrow][k0+kk]
#pragma unroll
        for (int i = 0; i < 4; i++) {
            float4 a4 = rowok ? *reinterpret_cast<const float4*>(&A[(size_t)myrow * K + k0 + i * 4])
                              : make_float4(0.f, 0.f, 0.f, 0.f);
            As[(i * 4 + 0) * 256 + tid] = a4.x;
            As[(i * 4 + 1) * 256 + tid] = a4.y;
            As[(i * 4 + 2) * 256 + tid] = a4.z;
            As[(i * 4 + 3) * 256 + tid] = a4.w;
        }
        __syncthreads();
#pragma unroll
        for (int kk = 0; kk < 16; kk++) {
            float4 av = *reinterpret_cast<const float4*>(&As[kk * 256 + nodegrp * 4]);
            const ulonglong2* wr = &Ws[(k0 + kk) * 16 + colgrp * 4];
            ulonglong2 w0 = wr[0], w1 = wr[1], w2 = wr[2], w3 = wr[3];
            unsigned long long wp0 = w0.x, wp1 = w0.y, wp2 = w1.x, wp3 = w1.y;
            unsigned long long wp4 = w2.x, wp5 = w2.y, wp6 = w3.x, wp7 = w3.y;
            float an[4] = {av.x, av.y, av.z, av.w};
#pragma unroll
            for (int i = 0; i < 4; i++) {
                unsigned long long a2;
                asm("mov.b64 %0, {%1, %1};" : "=l"(a2) : "f"(an[i]));
                asm("fma.rn.f32x2 %0, %1, %2, %0;" : "+l"(acc[i*8+0]) : "l"(a2), "l"(wp0));
                asm("fma.rn.f32x2 %0, %1, %2, %0;" : "+l"(acc[i*8+1]) : "l"(a2), "l"(wp1));
                asm("fma.rn.f32x2 %0, %1, %2, %0;" : "+l"(acc[i*8+2]) : "l"(a2), "l"(wp2));
                asm("fma.rn.f32x2 %0, %1, %2, %0;" : "+l"(acc[i*8+3]) : "l"(a2), "l"(wp3));
                asm("fma.rn.f32x2 %0, %1, %2, %0;" : "+l"(acc[i*8+4]) : "l"(a2), "l"(wp4));
                asm("fma.rn.f32x2 %0, %1, %2, %0;" : "+l"(acc[i*8+5]) : "l"(a2), "l"(wp5));
                asm("fma.rn.f32x2 %0, %1, %2, %0;" : "+l"(acc[i*8+6]) : "l"(a2), "l"(wp6));
                asm("fma.rn.f32x2 %0, %1, %2, %0;" : "+l"(acc[i*8+7]) : "l"(a2), "l"(wp7));
            }
        }
    }

    int gnBase = nodeBase + nodegrp * 4;
    if (HALF_OUT) {
#pragma unroll
        for (int i = 0; i < 4; i++) {
            int gn = gnBase + i;
            if (gn >= n) break;
            float s = rsqrtf((float)__ldg(&cnt[gn]) + 1.0f);
            unsigned u[8];
#pragma unroll
            for (int p = 0; p < 8; p++) {
                float lo, hi;
                asm("mov.b64 {%0, %1}, %2;" : "=f"(lo), "=f"(hi) : "l"(acc[i*8+p]));
                __half2 h = __floats2half2_rn(lo * s, hi * s);
                u[p] = *reinterpret_cast<unsigned*>(&h);
            }
            uint4* o = reinterpret_cast<uint4*>((__half*)out + (size_t)gn * 64 + colgrp * 16);
            o[0] = make_uint4(u[0], u[1], u[2], u[3]);
            o[1] = make_uint4(u[4], u[5], u[6], u[7]);
        }
    } else {
        const float4* b4 = reinterpret_cast<const float4*>(bias) + colgrp * 4;
        float4 bb[4] = {b4[0], b4[1], b4[2], b4[3]};
#pragma unroll
        for (int i = 0; i < 4; i++) {
            int gn = gnBase + i;
            if (gn >= n) break;
            float4* o = reinterpret_cast<float4*>((float*)out + (size_t)gn * 64 + colgrp * 16);
#pragma unroll
            for (int q = 0; q < 4; q++) {
                float lo0, hi0, lo1, hi1;
                asm("mov.b64 {%0, %1}, %2;" : "=f"(lo0), "=f"(hi0) : "l"(acc[i*8+2*q]));
                asm("mov.b64 {%0, %1}, %2;" : "=f"(lo1), "=f"(hi1) : "l"(acc[i*8+2*q+1]));
                o[q] = make_float4(lo0 + bb[q].x, hi0 + bb[q].y, lo1 + bb[q].z, hi1 + bb[q].w);
            }
        }
    }
}

// ---------------- fused gather + self + bias + LN + ReLU (+skip+readout) -------------
// (round-7 version: warp/node, 32-batch shfl-distributed indices, fp16 HADD2 accum)
__global__ void __launch_bounds__(256) k_gather(const float* __restrict__ bias,
                                                const float* __restrict__ lng,
                                                const float* __restrict__ lnb,
                                                float* __restrict__ outh, int n,
                                                int do_readout,
                                                const void* __restrict__ batch) {
    const unsigned FULL = 0xffffffffu;
    int t = blockIdx.x * blockDim.x + threadIdx.x;
    int node = t >> 5, lane = t & 31;
    if (node >= n) return;

    int start = g_ptr[node];
    int cnt   = g_cnt[node];
    const __half2* hw = (const __half2*)g_hws;
    size_t off = (size_t)node * 32 + lane;

    __half2 h0 = __float2half2_rn(0.f);
    __half2 h1 = h0, h2 = h0, h3 = h0;

    int done = 0;
    while (done < cnt) {
        int m = cnt - done;
        if (m > 32) m = 32;
        int bidx = 0;
        if (lane < m) bidx = __ldg(&g_csr_src[start + done + lane]);

        int j = 0;
        for (; j + 8 <= m; j += 8) {
            int s0 = __shfl_sync(FULL, bidx, j);
            int s1 = __shfl_sync(FULL, bidx, j + 1);
            int s2 = __shfl_sync(FULL, bidx, j + 2);
            int s3 = __shfl_sync(FULL, bidx, j + 3);
            int s4 = __shfl_sync(FULL, bidx, j + 4);
            int s5 = __shfl_sync(FULL, bidx, j + 5);
            int s6 = __shfl_sync(FULL, bidx, j + 6);
            int s7 = __shfl_sync(FULL, bidx, j + 7);
            __half2 v0 = __ldg(&hw[(size_t)s0 * 32 + lane]);
            __half2 v1 = __ldg(&hw[(size_t)s1 * 32 + lane]);
            __half2 v2 = __ldg(&hw[(size_t)s2 * 32 + lane]);
            __half2 v3 = __ldg(&hw[(size_t)s3 * 32 + lane]);
            __half2 v4 = __ldg(&hw[(size_t)s4 * 32 + lane]);
            __half2 v5 = __ldg(&hw[(size_t)s5 * 32 + lane]);
            __half2 v6 = __ldg(&hw[(size_t)s6 * 32 + lane]);
            __half2 v7 = __ldg(&hw[(size_t)s7 * 32 + lane]);
            h0 = __hadd2(h0, v0);
            h1 = __hadd2(h1, v1);
            h2 = __hadd2(h2, v2);
            h3 = __hadd2(h3, v3);
            h0 = __hadd2(h0, v4);
            h1 = __hadd2(h1, v5);
            h2 = __hadd2(h2, v6);
            h3 = __hadd2(h3, v7);
        }
        for (; j + 2 <= m; j += 2) {
            int s0 = __shfl_sync(FULL, bidx, j);
            int s1 = __shfl_sync(FULL, bidx, j + 1);
            __half2 v0 = __ldg(&hw[(size_t)s0 * 32 + lane]);
            __half2 v1 = __ldg(&hw[(size_t)s1 * 32 + lane]);
            h0 = __hadd2(h0, v0);
            h1 = __hadd2(h1, v1);
        }
        if (j < m) {
            int s0 = __shfl_sync(FULL, bidx, j);
            h0 = __hadd2(h0, __ldg(&hw[(size_t)s0 * 32 + lane]));
        }
        done += m;
    }

    float2 f0 = __half22float2(h0);
    float2 f1 = __half22float2(h1);
    float2 f2 = __half22float2(h2);
    float2 f3 = __half22float2(h3);
    float2 self = __half22float2(__ldg(&hw[off]));
    float accx = ((f0.x + f1.x) + (f2.x + f3.x)) + self.x;
    float accy = ((f0.y + f1.y) + (f2.y + f3.y)) + self.y;

    float isqn = g_deg[node];
    float2 bb = ((const float2*)bias)[lane];
    float vx = fmaf(isqn, accx, bb.x);
    float vy = fmaf(isqn, accy, bb.y);

    float sum = vx + vy;
#pragma unroll
    for (int o = 16; o; o >>= 1) sum += __shfl_xor_sync(FULL, sum, o);
    float mu = sum * (1.0f / 64.0f);

    float dx = vx - mu, dy = vy - mu;
    float var = dx * dx + dy * dy;
#pragma unroll
    for (int o = 16; o; o >>= 1) var += __shfl_xor_sync(FULL, var, o);
    float rstd = rsqrtf(var * (1.0f / 64.0f) + 1e-5f);

    float2 gg = ((const float2*)lng)[lane];
    float2 lb = ((const float2*)lnb)[lane];
    float ox = fmaxf(fmaf(dx * rstd, gg.x, lb.x), 0.f);
    float oy = fmaxf(fmaf(dy * rstd, gg.y, lb.y), 0.f);

    if (!do_readout) {
        ((float2*)outh)[off] = make_float2(ox, oy);
    } else {
        float2 h1v = ((const float2*)g_h1)[off];
        float2 sk = make_float2(ox + h1v.x, oy + h1v.y);
        int grp = g_idx32 ? ((const int*)batch)[node]
                          : (int)((const long long*)batch)[node];
        atomicAdd(((float2*)g_readout) + (size_t)grp * 32 + lane, sk);
    }
}

// ---------------- post GEMM ----------------
__global__ void k_post(const float* __restrict__ W, const float* __restrict__ b,
                       float* __restrict__ out, int G) {
    __shared__ float r[64];
    int g = blockIdx.x;
    r[threadIdx.x] = g_readout[(size_t)g * 64 + threadIdx.x];
    __syncthreads();
    int c = threadIdx.x;
    if (c < 40) {
        float acc = b[c];
#pragma unroll
        for (int k = 0; k < 64; k++) acc = fmaf(r[k], __ldg(&W[k * 40 + c]), acc);
        out[(size_t)g * 40 + c] = acc;
    }
}

// ---------------- launch: hist(1) scan(2) fill(3) pregemm(4) gemm1(5) ... ------------
extern "C" void kernel_launch(void* const* d_in, const int* in_sizes, int n_in,
                              void* d_out, int out_size) {
    const float* x      = (const float*)d_in[0];
    const void*  eidx   = d_in[1];
    const void*  batch  = d_in[2];
    const float* pre_w  = (const float*)d_in[3];
    const float* pre_b  = (const float*)d_in[4];
    const float* c1_w   = (const float*)d_in[5];
    const float* c1_b   = (const float*)d_in[6];
    const float* n1_g   = (const float*)d_in[7];
    const float* n1_b   = (const float*)d_in[8];
    const float* c2_w   = (const float*)d_in[9];
    const float* c2_b   = (const float*)d_in[10];
    const float* n2_g   = (const float*)d_in[11];
    const float* n2_b   = (const float*)d_in[12];
    const float* post_w = (const float*)d_in[13];
    const float* post_b = (const float*)d_in[14];

    int N = in_sizes[0] / 128;
    int E = in_sizes[1] / 2;
    int G = out_size / 40;

    float *p_h, *p_h1, *p_readout;
    __half* p_hws;
    int *p_cnt, *p_flag;
    cudaGetSymbolAddress((void**)&p_h,       g_h);
    cudaGetSymbolAddress((void**)&p_hws,     g_hws);
    cudaGetSymbolAddress((void**)&p_h1,      g_h1);
    cudaGetSymbolAddress((void**)&p_cnt,     g_cnt);
    cudaGetSymbolAddress((void**)&p_flag,    g_scanflag);
    cudaGetSymbolAddress((void**)&p_readout, g_readout);

    static cudaStream_t s1 = nullptr, s2 = nullptr;
    static cudaEvent_t evFork = nullptr, evHist = nullptr, evG1 = nullptr, evCsr = nullptr;
    if (!s1) {
        cudaStreamCreateWithFlags(&s1, cudaStreamNonBlocking);
        cudaStreamCreateWithFlags(&s2, cudaStreamNonBlocking);
        cudaEventCreateWithFlags(&evFork, cudaEventDisableTiming);
        cudaEventCreateWithFlags(&evHist, cudaEventDisableTiming);
        cudaEventCreateWithFlags(&evG1,   cudaEventDisableTiming);
        cudaEventCreateWithFlags(&evCsr,  cudaEventDisableTiming);
    }

    cudaEventRecord(evFork, 0);
    cudaStreamWaitEvent(s1, evFork, 0);
    cudaStreamWaitEvent(s2, evFork, 0);

    // --- s2: memsets + CSR build (kernels #1-#3) ---
    cudaMemsetAsync(p_cnt, 0, (size_t)N * 4, s2);
    cudaMemsetAsync(p_flag, 0, 128 * 4, s2);
    cudaMemsetAsync(p_readout, 0, (size_t)G * 64 * 4, s2);
    k_hist<<<(E + 1023) / 1024, 256, 0, s2>>>(eidx, E, (long long)N);
    cudaEventRecord(evHist, s2);
    k_scan<<<(N + 1023) / 1024, 256, 0, s2>>>(N);
    k_fill<<<(E + 1023) / 1024, 256, 0, s2>>>(eidx, E, (long long)N);
    cudaEventRecord(evCsr, s2);

    // --- s1: pre-GEMM (#4, ncu target), gemm1 (#5, needs only hist counts) ---
    k_gemm<128, 0><<<(N + 255) / 256, 256, 0, s1>>>(x, pre_w, pre_b, nullptr, p_h, N);
    cudaStreamWaitEvent(s1, evHist, 0);
    k_gemm<64, 1><<<(N + 255) / 256, 256, 0, s1>>>(p_h, c1_w, nullptr, p_cnt, p_hws, N);
    cudaEventRecord(evG1, s1);

    // --- join on origin stream ---
    cudaStreamWaitEvent(0, evG1, 0);
    cudaStreamWaitEvent(0, evCsr, 0);

    // layer 1 gather -> h1 (#6)
    k_gather<<<((size_t)N * 32 + 255) / 256, 256>>>(c1_b, n1_g, n1_b, p_h1, N, 0, nullptr);

    // layer 2 (#7, #8)
    k_gemm<64, 1><<<(N + 255) / 256, 256>>>(p_h1, c2_w, nullptr, p_cnt, p_hws, N);
    k_gather<<<((size_t)N * 32 + 255) / 256, 256>>>(c2_b, n2_g, n2_b, nullptr, N, 1, batch);

    // post (#9)
    k_post<<<G, 64>>>(post_w, post_b, (float*)d_out, G);
}

// round 10
// speedup vs baseline: 1.5638x; 1.3799x over previous
#include <cuda_runtime.h>
#include <cuda_fp16.h>
#include <mma.h>
#include <cstdint>
#include <cstddef>

using namespace nvcuda;

// Problem constants: N=100000, E=1600000, F=128, H=64, C=40, G=2048
#define NMAX 100000
#define EMAX 1600000
#define GMAX 2048

// ---------------- scratch (device globals; no runtime alloc allowed) ----------------
__device__ __align__(128) float  g_h  [NMAX * 64];   // pre-MLP output (fp32)
__device__ __align__(128) __half g_hws[NMAX * 64];   // (h @ W) * isq (fp16) per layer
__device__ __align__(128) float  g_h1 [NMAX * 64];   // layer-1 activations (for skip)
__device__ __align__(16)  float  g_deg[NMAX];        // isq
__device__ __align__(128) float  g_readout[GMAX * 64];
__device__ __align__(16)  int    g_cnt[NMAX];        // per-dst degree
__device__ __align__(16)  int    g_ptr[NMAX];        // CSR row starts
__device__ __align__(16)  int    g_cursor[NMAX];     // fill cursors
__device__ __align__(16)  int    g_csr_src[EMAX];    // CSR column (src) indices
__device__ int g_scanflag[128];                      // lookback published aggregates (+1)
__device__ int g_idx32;                              // 1 if indices are int32

// ---------------- per-block index-dtype detection ----------------
__device__ __forceinline__ int block_detect_idx32(const void* e, int E, long long nlim,
                                                  int* s_flag) {
    if (threadIdx.x == 0) *s_flag = 0;
    __syncthreads();
    int m = E < 64 ? E : 64;
    if ((int)threadIdx.x < m) {
        long long v = ((const long long*)e)[threadIdx.x];
        if (v < 0 || v >= nlim) *s_flag = 1;
    }
    __syncthreads();
    return *s_flag;
}

// ---------------- degree histogram (4 edges/thread; block 0 publishes g_idx32) -------
__global__ void __launch_bounds__(256) k_hist(const void* __restrict__ eidx, int E,
                                              long long nlim) {
    __shared__ int sf;
    int idx32 = block_detect_idx32(eidx, E, nlim, &sf);
    if (blockIdx.x == 0 && threadIdx.x == 0) g_idx32 = idx32;
    int base = (blockIdx.x * blockDim.x + threadIdx.x) * 4;
    if (idx32) {
        const int* d = (const int*)eidx + E;
#pragma unroll
        for (int k = 0; k < 4; k++) {
            int e = base + k;
            if (e < E) atomicAdd(&g_cnt[d[e]], 1);
        }
    } else {
        const long long* d = (const long long*)eidx + E;
#pragma unroll
        for (int k = 0; k < 4; k++) {
            int e = base + k;
            if (e < E) atomicAdd(&g_cnt[(int)d[e]], 1);
        }
    }
}

// ---------------- single-pass exclusive scan (lookback) + cursor + isq ----------------
__global__ void __launch_bounds__(256) k_scan(int n) {
    __shared__ int wsum[8];
    __shared__ int red[8];
    __shared__ int s_prefix;
    int bid = blockIdx.x;
    int base = bid * 1024 + threadIdx.x * 4;

    int c0 = 0, c1 = 0, c2 = 0, c3 = 0;
    if (base + 3 < n) {
        int4 c = *(const int4*)&g_cnt[base];
        c0 = c.x; c1 = c.y; c2 = c.z; c3 = c.w;
    } else if (base < n) {
        c0 = g_cnt[base];
        if (base + 1 < n) c1 = g_cnt[base + 1];
        if (base + 2 < n) c2 = g_cnt[base + 2];
    }
    int tot = c0 + c1 + c2 + c3;
    int lane = threadIdx.x & 31, wid = threadIdx.x >> 5;
    int v = tot;
#pragma unroll
    for (int o = 1; o < 32; o <<= 1) {
        int u = __shfl_up_sync(0xffffffffu, v, o);
        if (lane >= o) v += u;
    }
    if (lane == 31) wsum[wid] = v;
    __syncthreads();
    if (threadIdx.x == 0) {
        int s = 0;
        for (int i = 0; i < 8; i++) { int t = wsum[i]; wsum[i] = s; s += t; }
        atomicExch(&g_scanflag[bid], s + 1);
    }
    __syncthreads();

    int part = 0;
    if ((int)threadIdx.x < bid) {
        volatile int* f = &g_scanflag[threadIdx.x];
        int x;
        do { x = *f; } while (x == 0);
        part = x - 1;
    }
#pragma unroll
    for (int o = 16; o; o >>= 1) part += __shfl_xor_sync(0xffffffffu, part, o);
    if (lane == 0) red[wid] = part;
    __syncthreads();
    if (threadIdx.x == 0) {
        int s = 0;
        for (int i = 0; i < 8; i++) s += red[i];
        s_prefix = s;
    }
    __syncthreads();

    int excl = v - tot + wsum[wid] + s_prefix;
    if (base < n) {
        int p0 = excl, p1 = p0 + c0, p2 = p1 + c1, p3 = p2 + c2;
        g_ptr[base] = p0; g_cursor[base] = p0; g_deg[base] = rsqrtf((float)c0 + 1.0f);
        if (base + 1 < n) { g_ptr[base+1] = p1; g_cursor[base+1] = p1; g_deg[base+1] = rsqrtf((float)c1 + 1.0f); }
        if (base + 2 < n) { g_ptr[base+2] = p2; g_cursor[base+2] = p2; g_deg[base+2] = rsqrtf((float)c2 + 1.0f); }
        if (base + 3 < n) { g_ptr[base+3] = p3; g_cursor[base+3] = p3; g_deg[base+3] = rsqrtf((float)c3 + 1.0f); }
    }
}

// ---------------- CSR fill (4 edges/thread, full grid) ----------------
__global__ void __launch_bounds__(256) k_fill(const void* __restrict__ eidx, int E,
                                              long long nlim) {
    __shared__ int sf;
    int idx32 = block_detect_idx32(eidx, E, nlim, &sf);
    int base = (blockIdx.x * blockDim.x + threadIdx.x) * 4;
#pragma unroll
    for (int k = 0; k < 4; k++) {
        int e = base + k;
        if (e >= E) break;
        int src, dst;
        if (idx32) {
            const int* p = (const int*)eidx;
            src = p[e]; dst = p[E + e];
        } else {
            const long long* p = (const long long*)eidx;
            src = (int)p[e]; dst = (int)p[E + e];
        }
        int pos = atomicAdd(&g_cursor[dst], 1);
        g_csr_src[pos] = src;
    }
}

// ---------------- WMMA GEMM: out[n,64] = A[n,K] @ W[K,64], fp16 in / fp32 acc --------
// 256 thr = 8 warps; block covers 128 rows; warp computes 16 rows x 64 cols (4 frags).
// W staged fp16 SMEM ld=72 (bank stagger); A tile fp16 ld=24. Epilogue via SMEM
// (aliased over Ws/As): HALF_OUT -> *rsqrt(cnt+1) fp16, else +bias fp32.
template<int K, int HALF_OUT>
__global__ void __launch_bounds__(256) k_gemm(const float* __restrict__ A,
                                              const float* __restrict__ W,
                                              const float* __restrict__ bias,
                                              const int* __restrict__ cnt,
                                              void* __restrict__ out, int n) {
    constexpr int WS_H = K * 72;          // halfs
    constexpr int AS_H = 128 * 24;        // halfs
    constexpr int SM_A = (WS_H + AS_H) * 2;
    constexpr int SM_B = 8 * 16 * 72 * 4; // epilogue floats
    constexpr int SM_BYTES = SM_A > SM_B ? SM_A : SM_B;
    __shared__ __align__(16) char smbuf[SM_BYTES];
    __half* Ws = (__half*)smbuf;
    __half* As = (__half*)(smbuf) + WS_H;
    float*  Es = (float*)smbuf;

    int tid = threadIdx.x;
    int warpId = tid >> 5, lane = tid & 31;
    int nodeBase = blockIdx.x * 128;

    // stage W fp32 -> fp16, rows padded to 72
    for (int i = tid; i < K * 64; i += 256) {
        int r = i >> 6, c = i & 63;
        Ws[r * 72 + c] = __float2half(W[i]);
    }

    wmma::fragment<wmma::accumulator, 16, 16, 16, float> cf[4];
#pragma unroll
    for (int t = 0; t < 4; t++) wmma::fill_fragment(cf[t], 0.0f);

    // A staging assignment: thread -> (row, 8-col half)
    int srow = tid >> 1;
    int shalf = (tid & 1) * 8;
    int sgn = nodeBase + srow;
    bool sok = (sgn < n);
    const float* aptr = A + (size_t)sgn * K + shalf;

    for (int k0 = 0; k0 < K; k0 += 16) {
        __syncthreads();
        float4 f0, f1;
        if (sok) {
            f0 = *(const float4*)(aptr + k0);
            f1 = *(const float4*)(aptr + k0 + 4);
        } else {
            f0 = make_float4(0.f, 0.f, 0.f, 0.f);
            f1 = f0;
        }
        __align__(16) __half2 hs[4];
        hs[0] = __floats2half2_rn(f0.x, f0.y);
        hs[1] = __floats2half2_rn(f0.z, f0.w);
        hs[2] = __floats2half2_rn(f1.x, f1.y);
        hs[3] = __floats2half2_rn(f1.z, f1.w);
        *(uint4*)(As + srow * 24 + shalf) = *(const uint4*)hs;
        __syncthreads();

        wmma::fragment<wmma::matrix_a, 16, 16, 16, __half, wmma::row_major> af;
        wmma::load_matrix_sync(af, As + warpId * 16 * 24, 24);
#pragma unroll
        for (int t = 0; t < 4; t++) {
            wmma::fragment<wmma::matrix_b, 16, 16, 16, __half, wmma::row_major> bf;
            wmma::load_matrix_sync(bf, Ws + k0 * 72 + t * 16, 72);
            wmma::mma_sync(cf[t], af, bf, cf[t]);
        }
    }

    // epilogue: SMEM roundtrip (aliases Ws/As -> must sync all warps first)
    __syncthreads();
#pragma unroll
    for (int t = 0; t < 4; t++)
        wmma::store_matrix_sync(Es + warpId * 16 * 72 + t * 16, cf[t], 72,
                                wmma::mem_row_major);
    __syncwarp();

    int erow = lane >> 1;
    int ecol = (lane & 1) * 32;
    int gn = nodeBase + warpId * 16 + erow;
    if (gn < n) {
        const float* src = Es + warpId * 16 * 72 + erow * 72 + ecol;
        if (HALF_OUT) {
            float s = rsqrtf((float)__ldg(&cnt[gn]) + 1.0f);
            __half* o = (__half*)out + (size_t)gn * 64 + ecol;
#pragma unroll
            for (int q = 0; q < 4; q++) {
                float4 va = *(const float4*)(src + q * 8);
                float4 vb = *(const float4*)(src + q * 8 + 4);
                __align__(16) __half2 p[4];
                p[0] = __floats2half2_rn(va.x * s, va.y * s);
                p[1] = __floats2half2_rn(va.z * s, va.w * s);
                p[2] = __floats2half2_rn(vb.x * s, vb.y * s);
                p[3] = __floats2half2_rn(vb.z * s, vb.w * s);
                *(uint4*)(o + q * 8) = *(const uint4*)p;
            }
        } else {
            float* o = (float*)out + (size_t)gn * 64 + ecol;
            const float4* b4 = (const float4*)(bias + ecol);
#pragma unroll
            for (int q = 0; q < 8; q++) {
                float4 v = *(const float4*)(src + q * 4);
                float4 b = b4[q];
                *(float4*)(o + q * 4) = make_float4(v.x + b.x, v.y + b.y,
                                                    v.z + b.z, v.w + b.w);
            }
        }
    }
}

// ---------------- fused gather + self + bias + LN + ReLU (+skip+readout) -------------
// warp/node, 32-batch shfl-distributed indices, fp16 HADD2 accum, fp32 combine.
__global__ void __launch_bounds__(256) k_gather(const float* __restrict__ bias,
                                                const float* __restrict__ lng,
                                                const float* __restrict__ lnb,
                                                float* __restrict__ outh, int n,
                                                int do_readout,
                                                const void* __restrict__ batch) {
    const unsigned FULL = 0xffffffffu;
    int t = blockIdx.x * blockDim.x + threadIdx.x;
    int node = t >> 5, lane = t & 31;
    if (node >= n) return;

    int start = g_ptr[node];
    int cnt   = g_cnt[node];
    const __half2* hw = (const __half2*)g_hws;
    size_t off = (size_t)node * 32 + lane;

    __half2 h0 = __float2half2_rn(0.f);
    __half2 h1 = h0, h2 = h0, h3 = h0;

    int done = 0;
    while (done < cnt) {
        int m = cnt - done;
        if (m > 32) m = 32;
        int bidx = 0;
        if (lane < m) bidx = __ldg(&g_csr_src[start + done + lane]);

        int j = 0;
        for (; j + 8 <= m; j += 8) {
            int s0 = __shfl_sync(FULL, bidx, j);
            int s1 = __shfl_sync(FULL, bidx, j + 1);
            int s2 = __shfl_sync(FULL, bidx, j + 2);
            int s3 = __shfl_sync(FULL, bidx, j + 3);
            int s4 = __shfl_sync(FULL, bidx, j + 4);
            int s5 = __shfl_sync(FULL, bidx, j + 5);
            int s6 = __shfl_sync(FULL, bidx, j + 6);
            int s7 = __shfl_sync(FULL, bidx, j + 7);
            __half2 v0 = __ldg(&hw[(size_t)s0 * 32 + lane]);
            __half2 v1 = __ldg(&hw[(size_t)s1 * 32 + lane]);
            __half2 v2 = __ldg(&hw[(size_t)s2 * 32 + lane]);
            __half2 v3 = __ldg(&hw[(size_t)s3 * 32 + lane]);
            __half2 v4 = __ldg(&hw[(size_t)s4 * 32 + lane]);
            __half2 v5 = __ldg(&hw[(size_t)s5 * 32 + lane]);
            __half2 v6 = __ldg(&hw[(size_t)s6 * 32 + lane]);
            __half2 v7 = __ldg(&hw[(size_t)s7 * 32 + lane]);
            h0 = __hadd2(h0, v0);
            h1 = __hadd2(h1, v1);
            h2 = __hadd2(h2, v2);
            h3 = __hadd2(h3, v3);
            h0 = __hadd2(h0, v4);
            h1 = __hadd2(h1, v5);
            h2 = __hadd2(h2, v6);
            h3 = __hadd2(h3, v7);
        }
        for (; j + 2 <= m; j += 2) {
            int s0 = __shfl_sync(FULL, bidx, j);
            int s1 = __shfl_sync(FULL, bidx, j + 1);
            __half2 v0 = __ldg(&hw[(size_t)s0 * 32 + lane]);
            __half2 v1 = __ldg(&hw[(size_t)s1 * 32 + lane]);
            h0 = __hadd2(h0, v0);
            h1 = __hadd2(h1, v1);
        }
        if (j < m) {
            int s0 = __shfl_sync(FULL, bidx, j);
            h0 = __hadd2(h0, __ldg(&hw[(size_t)s0 * 32 + lane]));
        }
        done += m;
    }

    float2 f0 = __half22float2(h0);
    float2 f1 = __half22float2(h1);
    float2 f2 = __half22float2(h2);
    float2 f3 = __half22float2(h3);
    float2 self = __half22float2(__ldg(&hw[off]));
    float accx = ((f0.x + f1.x) + (f2.x + f3.x)) + self.x;
    float accy = ((f0.y + f1.y) + (f2.y + f3.y)) + self.y;

    float isqn = g_deg[node];
    float2 bb = ((const float2*)bias)[lane];
    float vx = fmaf(isqn, accx, bb.x);
    float vy = fmaf(isqn, accy, bb.y);

    float sum = vx + vy;
#pragma unroll
    for (int o = 16; o; o >>= 1) sum += __shfl_xor_sync(FULL, sum, o);
    float mu = sum * (1.0f / 64.0f);

    float dx = vx - mu, dy = vy - mu;
    float var = dx * dx + dy * dy;
#pragma unroll
    for (int o = 16; o; o >>= 1) var += __shfl_xor_sync(FULL, var, o);
    float rstd = rsqrtf(var * (1.0f / 64.0f) + 1e-5f);

    float2 gg = ((const float2*)lng)[lane];
    float2 lb = ((const float2*)lnb)[lane];
    float ox = fmaxf(fmaf(dx * rstd, gg.x, lb.x), 0.f);
    float oy = fmaxf(fmaf(dy * rstd, gg.y, lb.y), 0.f);

    if (!do_readout) {
        ((float2*)outh)[off] = make_float2(ox, oy);
    } else {
        float2 h1v = ((const float2*)g_h1)[off];
        float2 sk = make_float2(ox + h1v.x, oy + h1v.y);
        int grp = g_idx32 ? ((const int*)batch)[node]
                          : (int)((const long long*)batch)[node];
        atomicAdd(((float2*)g_readout) + (size_t)grp * 32 + lane, sk);
    }
}

// ---------------- post GEMM ----------------
__global__ void k_post(const float* __restrict__ W, const float* __restrict__ b,
                       float* __restrict__ out, int G) {
    __shared__ float r[64];
    int g = blockIdx.x;
    r[threadIdx.x] = g_readout[(size_t)g * 64 + threadIdx.x];
    __syncthreads();
    int c = threadIdx.x;
    if (c < 40) {
        float acc = b[c];
#pragma unroll
        for (int k = 0; k < 64; k++) acc = fmaf(r[k], __ldg(&W[k * 40 + c]), acc);
        out[(size_t)g * 40 + c] = acc;
    }
}

// ---------------- launch: hist(1) scan(2) fill(3) pregemm(4) gemm1(5) ... ------------
extern "C" void kernel_launch(void* const* d_in, const int* in_sizes, int n_in,
                              void* d_out, int out_size) {
    const float* x      = (const float*)d_in[0];
    const void*  eidx   = d_in[1];
    const void*  batch  = d_in[2];
    const float* pre_w  = (const float*)d_in[3];
    const float* pre_b  = (const float*)d_in[4];
    const float* c1_w   = (const float*)d_in[5];
    const float* c1_b   = (const float*)d_in[6];
    const float* n1_g   = (const float*)d_in[7];
    const float* n1_b   = (const float*)d_in[8];
    const float* c2_w   = (const float*)d_in[9];
    const float* c2_b   = (const float*)d_in[10];
    const float* n2_g   = (const float*)d_in[11];
    const float* n2_b   = (const float*)d_in[12];
    const float* post_w = (const float*)d_in[13];
    const float* post_b = (const float*)d_in[14];

    int N = in_sizes[0] / 128;
    int E = in_sizes[1] / 2;
    int G = out_size / 40;

    float *p_h, *p_h1, *p_readout;
    __half* p_hws;
    int *p_cnt, *p_flag;
    cudaGetSymbolAddress((void**)&p_h,       g_h);
    cudaGetSymbolAddress((void**)&p_hws,     g_hws);
    cudaGetSymbolAddress((void**)&p_h1,      g_h1);
    cudaGetSymbolAddress((void**)&p_cnt,     g_cnt);
    cudaGetSymbolAddress((void**)&p_flag,    g_scanflag);
    cudaGetSymbolAddress((void**)&p_readout, g_readout);

    static cudaStream_t s1 = nullptr, s2 = nullptr;
    static cudaEvent_t evFork = nullptr, evHist = nullptr, evG1 = nullptr, evCsr = nullptr;
    if (!s1) {
        cudaStreamCreateWithFlags(&s1, cudaStreamNonBlocking);
        cudaStreamCreateWithFlags(&s2, cudaStreamNonBlocking);
        cudaEventCreateWithFlags(&evFork, cudaEventDisableTiming);
        cudaEventCreateWithFlags(&evHist, cudaEventDisableTiming);
        cudaEventCreateWithFlags(&evG1,   cudaEventDisableTiming);
        cudaEventCreateWithFlags(&evCsr,  cudaEventDisableTiming);
    }

    cudaEventRecord(evFork, 0);
    cudaStreamWaitEvent(s1, evFork, 0);
    cudaStreamWaitEvent(s2, evFork, 0);

    // --- s2: memsets + CSR build (kernels #1-#3) ---
    cudaMemsetAsync(p_cnt, 0, (size_t)N * 4, s2);
    cudaMemsetAsync(p_flag, 0, 128 * 4, s2);
    cudaMemsetAsync(p_readout, 0, (size_t)G * 64 * 4, s2);
    k_hist<<<(E + 1023) / 1024, 256, 0, s2>>>(eidx, E, (long long)N);
    cudaEventRecord(evHist, s2);
    k_scan<<<(N + 1023) / 1024, 256, 0, s2>>>(N);
    k_fill<<<(E + 1023) / 1024, 256, 0, s2>>>(eidx, E, (long long)N);
    cudaEventRecord(evCsr, s2);

    // --- s1: pre-GEMM (#4, ncu target), gemm1 (#5, needs only hist counts) ---
    k_gemm<128, 0><<<(N + 127) / 128, 256, 0, s1>>>(x, pre_w, pre_b, nullptr, p_h, N);
    cudaStreamWaitEvent(s1, evHist, 0);
    k_gemm<64, 1><<<(N + 127) / 128, 256, 0, s1>>>(p_h, c1_w, nullptr, p_cnt, p_hws, N);
    cudaEventRecord(evG1, s1);

    // --- join on origin stream ---
    cudaStreamWaitEvent(0, evG1, 0);
    cudaStreamWaitEvent(0, evCsr, 0);

    // layer 1 gather -> h1 (#6)
    k_gather<<<((size_t)N * 32 + 255) / 256, 256>>>(c1_b, n1_g, n1_b, p_h1, N, 0, nullptr);

    // layer 2 (#7, #8)
    k_gemm<64, 1><<<(N + 127) / 128, 256>>>(p_h1, c2_w, nullptr, p_cnt, p_hws, N);
    k_gather<<<((size_t)N * 32 + 255) / 256, 256>>>(c2_b, n2_g, n2_b, nullptr, N, 1, batch);

    // post (#9)
    k_post<<<G, 64>>>(post_w, post_b, (float*)d_out, G);
}

// round 11
// speedup vs baseline: 1.6016x; 1.0241x over previous
#include <cuda_runtime.h>
#include <cuda_fp16.h>
#include <mma.h>
#include <cstdint>
#include <cstddef>

using namespace nvcuda;

// Problem constants: N=100000, E=1600000, F=128, H=64, C=40, G=2048
#define NMAX 100000
#define EMAX 1600000
#define GMAX 2048

// ---------------- scratch (device globals; no runtime alloc allowed) ----------------
__device__ __align__(128) float  g_h  [NMAX * 64];   // pre-MLP output (fp32)
__device__ __align__(128) __half g_hws[NMAX * 64];   // (h @ W) * isq (fp16) per layer
__device__ __align__(128) float  g_h1 [NMAX * 64];   // layer-1 activations (for skip)
__device__ __align__(16)  float  g_deg[NMAX];        // isq
__device__ __align__(128) float  g_readout[GMAX * 64];
__device__ __align__(16)  int    g_cnt[NMAX];        // per-dst degree
__device__ __align__(16)  int    g_ptr[NMAX];        // CSR row starts
__device__ __align__(16)  int    g_cursor[NMAX];     // fill cursors
__device__ __align__(16)  int    g_csr_src[EMAX];    // CSR column (src) indices
__device__ int g_scanflag[128];                      // lookback published aggregates (+1)
__device__ int g_idx32;                              // 1 if indices are int32

// ---------------- per-block index-dtype detection ----------------
__device__ __forceinline__ int block_detect_idx32(const void* e, int E, long long nlim,
                                                  int* s_flag) {
    if (threadIdx.x == 0) *s_flag = 0;
    __syncthreads();
    int m = E < 64 ? E : 64;
    if ((int)threadIdx.x < m) {
        long long v = ((const long long*)e)[threadIdx.x];
        if (v < 0 || v >= nlim) *s_flag = 1;
    }
    __syncthreads();
    return *s_flag;
}

// ---------------- degree histogram (4 edges/thread; block 0 publishes g_idx32) -------
__global__ void __launch_bounds__(256) k_hist(const void* __restrict__ eidx, int E,
                                              long long nlim) {
    __shared__ int sf;
    int idx32 = block_detect_idx32(eidx, E, nlim, &sf);
    if (blockIdx.x == 0 && threadIdx.x == 0) g_idx32 = idx32;
    int base = (blockIdx.x * blockDim.x + threadIdx.x) * 4;
    if (idx32) {
        const int* d = (const int*)eidx + E;
#pragma unroll
        for (int k = 0; k < 4; k++) {
            int e = base + k;
            if (e < E) atomicAdd(&g_cnt[d[e]], 1);
        }
    } else {
        const long long* d = (const long long*)eidx + E;
#pragma unroll
        for (int k = 0; k < 4; k++) {
            int e = base + k;
            if (e < E) atomicAdd(&g_cnt[(int)d[e]], 1);
        }
    }
}

// ---------------- single-pass exclusive scan (lookback) + cursor + isq ----------------
__global__ void __launch_bounds__(256) k_scan(int n) {
    __shared__ int wsum[8];
    __shared__ int red[8];
    __shared__ int s_prefix;
    int bid = blockIdx.x;
    int base = bid * 1024 + threadIdx.x * 4;

    int c0 = 0, c1 = 0, c2 = 0, c3 = 0;
    if (base + 3 < n) {
        int4 c = *(const int4*)&g_cnt[base];
        c0 = c.x; c1 = c.y; c2 = c.z; c3 = c.w;
    } else if (base < n) {
        c0 = g_cnt[base];
        if (base + 1 < n) c1 = g_cnt[base + 1];
        if (base + 2 < n) c2 = g_cnt[base + 2];
    }
    int tot = c0 + c1 + c2 + c3;
    int lane = threadIdx.x & 31, wid = threadIdx.x >> 5;
    int v = tot;
#pragma unroll
    for (int o = 1; o < 32; o <<= 1) {
        int u = __shfl_up_sync(0xffffffffu, v, o);
        if (lane >= o) v += u;
    }
    if (lane == 31) wsum[wid] = v;
    __syncthreads();
    if (threadIdx.x == 0) {
        int s = 0;
        for (int i = 0; i < 8; i++) { int t = wsum[i]; wsum[i] = s; s += t; }
        atomicExch(&g_scanflag[bid], s + 1);
    }
    __syncthreads();

    int part = 0;
    if ((int)threadIdx.x < bid) {
        volatile int* f = &g_scanflag[threadIdx.x];
        int x;
        do { x = *f; } while (x == 0);
        part = x - 1;
    }
#pragma unroll
    for (int o = 16; o; o >>= 1) part += __shfl_xor_sync(0xffffffffu, part, o);
    if (lane == 0) red[wid] = part;
    __syncthreads();
    if (threadIdx.x == 0) {
        int s = 0;
        for (int i = 0; i < 8; i++) s += red[i];
        s_prefix = s;
    }
    __syncthreads();

    int excl = v - tot + wsum[wid] + s_prefix;
    if (base < n) {
        int p0 = excl, p1 = p0 + c0, p2 = p1 + c1, p3 = p2 + c2;
        g_ptr[base] = p0; g_cursor[base] = p0; g_deg[base] = rsqrtf((float)c0 + 1.0f);
        if (base + 1 < n) { g_ptr[base+1] = p1; g_cursor[base+1] = p1; g_deg[base+1] = rsqrtf((float)c1 + 1.0f); }
        if (base + 2 < n) { g_ptr[base+2] = p2; g_cursor[base+2] = p2; g_deg[base+2] = rsqrtf((float)c2 + 1.0f); }
        if (base + 3 < n) { g_ptr[base+3] = p3; g_cursor[base+3] = p3; g_deg[base+3] = rsqrtf((float)c3 + 1.0f); }
    }
}

// ---------------- CSR fill (4 edges/thread, full grid) ----------------
__global__ void __launch_bounds__(256) k_fill(const void* __restrict__ eidx, int E,
                                              long long nlim) {
    __shared__ int sf;
    int idx32 = block_detect_idx32(eidx, E, nlim, &sf);
    int base = (blockIdx.x * blockDim.x + threadIdx.x) * 4;
#pragma unroll
    for (int k = 0; k < 4; k++) {
        int e = base + k;
        if (e >= E) break;
        int src, dst;
        if (idx32) {
            const int* p = (const int*)eidx;
            src = p[e]; dst = p[E + e];
        } else {
            const long long* p = (const long long*)eidx;
            src = (int)p[e]; dst = (int)p[E + e];
        }
        int pos = atomicAdd(&g_cursor[dst], 1);
        g_csr_src[pos] = src;
    }
}

// ---------------- WMMA GEMM: out[n,64] = A[n,K] @ W[K,64], fp16 in / fp32 acc --------
// 256 thr = 8 warps; block covers 128 rows. A staged in 64-col chunks (2 syncs each),
// Ws staged once -> 5 barriers total for K=128. Epilogue via aliased SMEM.
template<int K, int HALF_OUT>
__global__ void __launch_bounds__(256) k_gemm(const float* __restrict__ A,
                                              const float* __restrict__ W,
                                              const float* __restrict__ bias,
                                              const int* __restrict__ cnt,
                                              void* __restrict__ out, int n) {
    constexpr int CH = 64;                         // A chunk columns
    constexpr int NCH = K / CH;
    constexpr int WS_H = K * 72;                   // halfs
    constexpr int AS_H = 128 * 72;                 // halfs
    constexpr int SM_A = (WS_H + AS_H) * 2;
    constexpr int SM_B = 8 * 16 * 72 * 4;          // epilogue floats
    constexpr int SM_BYTES = SM_A > SM_B ? SM_A : SM_B;
    __shared__ __align__(16) char smbuf[SM_BYTES];
    __half* Ws = (__half*)smbuf;
    __half* As = (__half*)smbuf + WS_H;
    float*  Es = (float*)smbuf;

    int tid = threadIdx.x;
    int warpId = tid >> 5, lane = tid & 31;
    int nodeBase = blockIdx.x * 128;

    // stage W fp32 -> fp16, rows padded to 72 (once)
    for (int i = tid; i < K * 64; i += 256) {
        int r = i >> 6, c = i & 63;
        Ws[r * 72 + c] = __float2half(W[i]);
    }

    wmma::fragment<wmma::accumulator, 16, 16, 16, float> cf[4];
#pragma unroll
    for (int t = 0; t < 4; t++) wmma::fill_fragment(cf[t], 0.0f);

    // A staging assignment: thread -> (row, 32-col half of chunk)
    int srow = tid >> 1;
    int scol = (tid & 1) * 32;
    int sgn = nodeBase + srow;
    bool sok = (sgn < n);
    const float* aptr = A + (size_t)sgn * K + scol;

#pragma unroll
    for (int c = 0; c < NCH; c++) {
        __syncthreads();
        // stage 64-col chunk: 32 floats/thread -> fp16
#pragma unroll
        for (int q = 0; q < 4; q++) {
            float4 f0, f1;
            if (sok) {
                f0 = *(const float4*)(aptr + c * CH + q * 8);
                f1 = *(const float4*)(aptr + c * CH + q * 8 + 4);
            } else {
                f0 = make_float4(0.f, 0.f, 0.f, 0.f);
                f1 = f0;
            }
            __align__(16) __half2 hs[4];
            hs[0] = __floats2half2_rn(f0.x, f0.y);
            hs[1] = __floats2half2_rn(f0.z, f0.w);
            hs[2] = __floats2half2_rn(f1.x, f1.y);
            hs[3] = __floats2half2_rn(f1.z, f1.w);
            *(uint4*)(As + srow * 72 + scol + q * 8) = *(const uint4*)hs;
        }
        __syncthreads();

#pragma unroll
        for (int kk = 0; kk < CH; kk += 16) {
            wmma::fragment<wmma::matrix_a, 16, 16, 16, __half, wmma::row_major> af;
            wmma::load_matrix_sync(af, As + warpId * 16 * 72 + kk, 72);
#pragma unroll
            for (int t = 0; t < 4; t++) {
                wmma::fragment<wmma::matrix_b, 16, 16, 16, __half, wmma::row_major> bf;
                wmma::load_matrix_sync(bf, Ws + (c * CH + kk) * 72 + t * 16, 72);
                wmma::mma_sync(cf[t], af, bf, cf[t]);
            }
        }
    }

    // epilogue: SMEM roundtrip (aliases Ws/As)
    __syncthreads();
#pragma unroll
    for (int t = 0; t < 4; t++)
        wmma::store_matrix_sync(Es + warpId * 16 * 72 + t * 16, cf[t], 72,
                                wmma::mem_row_major);
    __syncwarp();

    int erow = lane >> 1;
    int ecol = (lane & 1) * 32;
    int gn = nodeBase + warpId * 16 + erow;
    if (gn < n) {
        const float* src = Es + warpId * 16 * 72 + erow * 72 + ecol;
        if (HALF_OUT) {
            float s = rsqrtf((float)__ldg(&cnt[gn]) + 1.0f);
            __half* o = (__half*)out + (size_t)gn * 64 + ecol;
#pragma unroll
            for (int q = 0; q < 4; q++) {
                float4 va = *(const float4*)(src + q * 8);
                float4 vb = *(const float4*)(src + q * 8 + 4);
                __align__(16) __half2 p[4];
                p[0] = __floats2half2_rn(va.x * s, va.y * s);
                p[1] = __floats2half2_rn(va.z * s, va.w * s);
                p[2] = __floats2half2_rn(vb.x * s, vb.y * s);
                p[3] = __floats2half2_rn(vb.z * s, vb.w * s);
                *(uint4*)(o + q * 8) = *(const uint4*)p;
            }
        } else {
            float* o = (float*)out + (size_t)gn * 64 + ecol;
            const float4* b4 = (const float4*)(bias + ecol);
#pragma unroll
            for (int q = 0; q < 8; q++) {
                float4 v = *(const float4*)(src + q * 4);
                float4 b = b4[q];
                *(float4*)(o + q * 4) = make_float4(v.x + b.x, v.y + b.y,
                                                    v.z + b.z, v.w + b.w);
            }
        }
    }
}

// ---------------- fused gather + self + bias + LN + ReLU (+skip+readout) -------------
// 4 independent nodes per warp, 8 lanes x uint4 (16B) per row -> one LDG.128 per edge
// per group. Indices batch-loaded 8-per-group, shfl-distributed. Loop runs to the
// warp-max cnt with predicated loads (all lanes alive -> full-mask shfl safe).
__global__ void __launch_bounds__(256) k_gather(const float* __restrict__ bias,
                                                const float* __restrict__ lng,
                                                const float* __restrict__ lnb,
                                                float* __restrict__ outh, int n,
                                                int do_readout,
                                                const void* __restrict__ batch) {
    const unsigned FULL = 0xffffffffu;
    int t = blockIdx.x * blockDim.x + threadIdx.x;
    int node = t >> 3;              // 8 lanes per node
    int lane = threadIdx.x & 31;
    int grp = lane >> 3, sub = lane & 7;
    bool ok = (node < n);
    int nodec = ok ? node : (n - 1);   // clamp; suppress stores later

    int start = g_ptr[nodec];
    int cnt   = ok ? g_cnt[nodec] : 0;

    // warp-max cnt (groups hold equal values; xor 8,16 spans the 4 groups)
    int mmax = cnt;
    mmax = max(mmax, __shfl_xor_sync(FULL, mmax, 8));
    mmax = max(mmax, __shfl_xor_sync(FULL, mmax, 16));

    const uint4* hw4 = (const uint4*)g_hws;   // 8 x uint4 per 64-half row
    __half2 acc[4];
    __half2 z = __float2half2_rn(0.f);
#pragma unroll
    for (int k = 0; k < 4; k++) acc[k] = z;

    for (int done = 0; done < mmax; done += 8) {
        int b = 0;
        if (done + sub < cnt) b = __ldg(&g_csr_src[start + done + sub]);
        int lim = cnt - done;   // edges this batch for my node (may be <=0)
        uint4 v[8];
#pragma unroll
        for (int j = 0; j < 8; j++) {
            int s = __shfl_sync(FULL, b, (grp << 3) + j);
            v[j] = make_uint4(0u, 0u, 0u, 0u);
            if (j < lim) v[j] = __ldg(&hw4[(size_t)s * 8 + sub]);
        }
#pragma unroll
        for (int j = 0; j < 8; j++) {
            const __half2* p = (const __half2*)&v[j];
            acc[0] = __hadd2(acc[0], p[0]);
            acc[1] = __hadd2(acc[1], p[1]);
            acc[2] = __hadd2(acc[2], p[2]);
            acc[3] = __hadd2(acc[3], p[3]);
        }
    }

    // fp32 combine: + self (already isq-scaled), *isq, +bias
    uint4 sv = __ldg(&hw4[(size_t)nodec * 8 + sub]);
    const __half2* ps = (const __half2*)&sv;
    float isqn = g_deg[nodec];
    const float4* b4 = (const float4*)bias;
    float4 bl = __ldg(&b4[sub * 2]), bh = __ldg(&b4[sub * 2 + 1]);
    float bb[8] = {bl.x, bl.y, bl.z, bl.w, bh.x, bh.y, bh.z, bh.w};

    float v8[8];
#pragma unroll
    for (int k = 0; k < 4; k++) {
        float2 f  = __half22float2(acc[k]);
        float2 fs = __half22float2(ps[k]);
        v8[2 * k]     = fmaf(isqn, f.x + fs.x, bb[2 * k]);
        v8[2 * k + 1] = fmaf(isqn, f.y + fs.y, bb[2 * k + 1]);
    }

    // LayerNorm over 64 = 8 vals/lane x 8 lanes (intra-group shuffles)
    float sum = 0.f;
#pragma unroll
    for (int i = 0; i < 8; i++) sum += v8[i];
#pragma unroll
    for (int o = 4; o; o >>= 1) sum += __shfl_xor_sync(FULL, sum, o);
    float mu = sum * (1.0f / 64.0f);

    float var = 0.f, d8[8];
#pragma unroll
    for (int i = 0; i < 8; i++) { d8[i] = v8[i] - mu; var += d8[i] * d8[i]; }
#pragma unroll
    for (int o = 4; o; o >>= 1) var += __shfl_xor_sync(FULL, var, o);
    float rstd = rsqrtf(var * (1.0f / 64.0f) + 1e-5f);

    const float4* g4 = (const float4*)lng;
    const float4* l4 = (const float4*)lnb;
    float4 gl = __ldg(&g4[sub * 2]), gh = __ldg(&g4[sub * 2 + 1]);
    float4 ll = __ldg(&l4[sub * 2]), lh = __ldg(&l4[sub * 2 + 1]);
    float gg[8] = {gl.x, gl.y, gl.z, gl.w, gh.x, gh.y, gh.z, gh.w};
    float lb[8] = {ll.x, ll.y, ll.z, ll.w, lh.x, lh.y, lh.z, lh.w};

    float o8[8];
#pragma unroll
    for (int i = 0; i < 8; i++)
        o8[i] = fmaxf(fmaf(d8[i] * rstd, gg[i], lb[i]), 0.f);

    if (!ok) return;
    if (!do_readout) {
        float4* o4 = (float4*)(outh + (size_t)node * 64 + sub * 8);
        o4[0] = make_float4(o8[0], o8[1], o8[2], o8[3]);
        o4[1] = make_float4(o8[4], o8[5], o8[6], o8[7]);
    } else {
        const float4* h14 = (const float4*)(g_h1 + (size_t)node * 64 + sub * 8);
        float4 ha = __ldg(&h14[0]), hb = __ldg(&h14[1]);
        int grpi = g_idx32 ? ((const int*)batch)[node]
                           : (int)((const long long*)batch)[node];
        float4* r4 = (float4*)(g_readout + (size_t)grpi * 64 + sub * 8);
        atomicAdd(&r4[0], make_float4(o8[0] + ha.x, o8[1] + ha.y, o8[2] + ha.z, o8[3] + ha.w));
        atomicAdd(&r4[1], make_float4(o8[4] + hb.x, o8[5] + hb.y, o8[6] + hb.z, o8[7] + hb.w));
    }
}

// ---------------- post GEMM ----------------
__global__ void k_post(const float* __restrict__ W, const float* __restrict__ b,
                       float* __restrict__ out, int G) {
    __shared__ float r[64];
    int g = blockIdx.x;
    r[threadIdx.x] = g_readout[(size_t)g * 64 + threadIdx.x];
    __syncthreads();
    int c = threadIdx.x;
    if (c < 40) {
        float acc = b[c];
#pragma unroll
        for (int k = 0; k < 64; k++) acc = fmaf(r[k], __ldg(&W[k * 40 + c]), acc);
        out[(size_t)g * 40 + c] = acc;
    }
}

// ---------------- launch: hist(1) scan(2) fill(3) pregemm(4) gemm1(5) ... ------------
extern "C" void kernel_launch(void* const* d_in, const int* in_sizes, int n_in,
                              void* d_out, int out_size) {
    const float* x      = (const float*)d_in[0];
    const void*  eidx   = d_in[1];
    const void*  batch  = d_in[2];
    const float* pre_w  = (const float*)d_in[3];
    const float* pre_b  = (const float*)d_in[4];
    const float* c1_w   = (const float*)d_in[5];
    const float* c1_b   = (const float*)d_in[6];
    const float* n1_g   = (const float*)d_in[7];
    const float* n1_b   = (const float*)d_in[8];
    const float* c2_w   = (const float*)d_in[9];
    const float* c2_b   = (const float*)d_in[10];
    const float* n2_g   = (const float*)d_in[11];
    const float* n2_b   = (const float*)d_in[12];
    const float* post_w = (const float*)d_in[13];
    const float* post_b = (const float*)d_in[14];

    int N = in_sizes[0] / 128;
    int E = in_sizes[1] / 2;
    int G = out_size / 40;

    float *p_h, *p_h1, *p_readout;
    __half* p_hws;
    int *p_cnt, *p_flag;
    cudaGetSymbolAddress((void**)&p_h,       g_h);
    cudaGetSymbolAddress((void**)&p_hws,     g_hws);
    cudaGetSymbolAddress((void**)&p_h1,      g_h1);
    cudaGetSymbolAddress((void**)&p_cnt,     g_cnt);
    cudaGetSymbolAddress((void**)&p_flag,    g_scanflag);
    cudaGetSymbolAddress((void**)&p_readout, g_readout);

    static cudaStream_t s1 = nullptr, s2 = nullptr;
    static cudaEvent_t evFork = nullptr, evHist = nullptr, evG1 = nullptr, evCsr = nullptr;
    if (!s1) {
        cudaStreamCreateWithFlags(&s1, cudaStreamNonBlocking);
        cudaStreamCreateWithFlags(&s2, cudaStreamNonBlocking);
        cudaEventCreateWithFlags(&evFork, cudaEventDisableTiming);
        cudaEventCreateWithFlags(&evHist, cudaEventDisableTiming);
        cudaEventCreateWithFlags(&evG1,   cudaEventDisableTiming);
        cudaEventCreateWithFlags(&evCsr,  cudaEventDisableTiming);
    }

    cudaEventRecord(evFork, 0);
    cudaStreamWaitEvent(s1, evFork, 0);
    cudaStreamWaitEvent(s2, evFork, 0);

    // --- s2: memsets + CSR build (kernels #1-#3) ---
    cudaMemsetAsync(p_cnt, 0, (size_t)N * 4, s2);
    cudaMemsetAsync(p_flag, 0, 128 * 4, s2);
    cudaMemsetAsync(p_readout, 0, (size_t)G * 64 * 4, s2);
    k_hist<<<(E + 1023) / 1024, 256, 0, s2>>>(eidx, E, (long long)N);
    cudaEventRecord(evHist, s2);
    k_scan<<<(N + 1023) / 1024, 256, 0, s2>>>(N);
    k_fill<<<(E + 1023) / 1024, 256, 0, s2>>>(eidx, E, (long long)N);
    cudaEventRecord(evCsr, s2);

    // --- s1: pre-GEMM (#4, ncu target), gemm1 (#5, needs only hist counts) ---
    k_gemm<128, 0><<<(N + 127) / 128, 256, 0, s1>>>(x, pre_w, pre_b, nullptr, p_h, N);
    cudaStreamWaitEvent(s1, evHist, 0);
    k_gemm<64, 1><<<(N + 127) / 128, 256, 0, s1>>>(p_h, c1_w, nullptr, p_cnt, p_hws, N);
    cudaEventRecord(evG1, s1);

    // --- join on origin stream ---
    cudaStreamWaitEvent(0, evG1, 0);
    cudaStreamWaitEvent(0, evCsr, 0);

    // layer 1 gather -> h1 (#6)
    k_gather<<<((size_t)N * 8 + 255) / 256, 256>>>(c1_b, n1_g, n1_b, p_h1, N, 0, nullptr);

    // layer 2 (#7, #8)
    k_gemm<64, 1><<<(N + 127) / 128, 256>>>(p_h1, c2_w, nullptr, p_cnt, p_hws, N);
    k_gather<<<((size_t)N * 8 + 255) / 256, 256>>>(c2_b, n2_g, n2_b, nullptr, N, 1, batch);

    // post (#9)
    k_post<<<G, 64>>>(post_w, post_b, (float*)d_out, G);
}

// round 12
// speedup vs baseline: 1.8236x; 1.1386x over previous
#include <cuda_runtime.h>
#include <cuda_fp16.h>
#include <mma.h>
#include <cstdint>
#include <cstddef>

using namespace nvcuda;

// Problem constants: N=100000, E=1600000, F=128, H=64, C=40, G=2048
#define NMAX 100000
#define EMAX 1600000
#define GMAX 2048

// ---------------- scratch (device globals; no runtime alloc allowed) ----------------
__device__ __align__(128) __half g_hws[NMAX * 64];  // (h @ W) * isq (fp16) per layer
__device__ __align__(128) __half g_h1 [NMAX * 64];  // layer-1 activations (fp16)
__device__ __align__(16)  float  g_deg[NMAX];       // isq
__device__ __align__(128) float  g_readout[GMAX * 64];
__device__ __align__(16)  int    g_cnt[NMAX];       // per-dst degree
__device__ __align__(16)  int    g_ptr[NMAX];       // CSR row starts
__device__ __align__(16)  int    g_cursor[NMAX];    // fill cursors
__device__ __align__(16)  int    g_csr_src[EMAX];   // CSR column (src) indices
__device__ int g_scanflag[128];                     // lookback published aggregates (+1)
__device__ int g_idx32;                             // 1 if indices are int32

// ---------------- per-block index-dtype detection ----------------
__device__ __forceinline__ int block_detect_idx32(const void* e, int E, long long nlim,
                                                  int* s_flag) {
    if (threadIdx.x == 0) *s_flag = 0;
    __syncthreads();
    int m = E < 64 ? E : 64;
    if ((int)threadIdx.x < m) {
        long long v = ((const long long*)e)[threadIdx.x];
        if (v < 0 || v >= nlim) *s_flag = 1;
    }
    __syncthreads();
    return *s_flag;
}

// ---------------- degree histogram (4 edges/thread; block 0 publishes g_idx32) -------
__global__ void __launch_bounds__(256) k_hist(const void* __restrict__ eidx, int E,
                                              long long nlim) {
    __shared__ int sf;
    int idx32 = block_detect_idx32(eidx, E, nlim, &sf);
    if (blockIdx.x == 0 && threadIdx.x == 0) g_idx32 = idx32;
    int base = (blockIdx.x * blockDim.x + threadIdx.x) * 4;
    if (idx32) {
        const int* d = (const int*)eidx + E;
#pragma unroll
        for (int k = 0; k < 4; k++) {
            int e = base + k;
            if (e < E) atomicAdd(&g_cnt[d[e]], 1);
        }
    } else {
        const long long* d = (const long long*)eidx + E;
#pragma unroll
        for (int k = 0; k < 4; k++) {
            int e = base + k;
            if (e < E) atomicAdd(&g_cnt[(int)d[e]], 1);
        }
    }
}

// ---------------- single-pass exclusive scan (lookback) + cursor + isq ----------------
__global__ void __launch_bounds__(256) k_scan(int n) {
    __shared__ int wsum[8];
    __shared__ int red[8];
    __shared__ int s_prefix;
    int bid = blockIdx.x;
    int base = bid * 1024 + threadIdx.x * 4;

    int c0 = 0, c1 = 0, c2 = 0, c3 = 0;
    if (base + 3 < n) {
        int4 c = *(const int4*)&g_cnt[base];
        c0 = c.x; c1 = c.y; c2 = c.z; c3 = c.w;
    } else if (base < n) {
        c0 = g_cnt[base];
        if (base + 1 < n) c1 = g_cnt[base + 1];
        if (base + 2 < n) c2 = g_cnt[base + 2];
    }
    int tot = c0 + c1 + c2 + c3;
    int lane = threadIdx.x & 31, wid = threadIdx.x >> 5;
    int v = tot;
#pragma unroll
    for (int o = 1; o < 32; o <<= 1) {
        int u = __shfl_up_sync(0xffffffffu, v, o);
        if (lane >= o) v += u;
    }
    if (lane == 31) wsum[wid] = v;
    __syncthreads();
    if (threadIdx.x == 0) {
        int s = 0;
        for (int i = 0; i < 8; i++) { int t = wsum[i]; wsum[i] = s; s += t; }
        atomicExch(&g_scanflag[bid], s + 1);
    }
    __syncthreads();

    int part = 0;
    if ((int)threadIdx.x < bid) {
        volatile int* f = &g_scanflag[threadIdx.x];
        int x;
        do { x = *f; } while (x == 0);
        part = x - 1;
    }
#pragma unroll
    for (int o = 16; o; o >>= 1) part += __shfl_xor_sync(0xffffffffu, part, o);
    if (lane == 0) red[wid] = part;
    __syncthreads();
    if (threadIdx.x == 0) {
        int s = 0;
        for (int i = 0; i < 8; i++) s += red[i];
        s_prefix = s;
    }
    __syncthreads();

    int excl = v - tot + wsum[wid] + s_prefix;
    if (base < n) {
        int p0 = excl, p1 = p0 + c0, p2 = p1 + c1, p3 = p2 + c2;
        g_ptr[base] = p0; g_cursor[base] = p0; g_deg[base] = rsqrtf((float)c0 + 1.0f);
        if (base + 1 < n) { g_ptr[base+1] = p1; g_cursor[base+1] = p1; g_deg[base+1] = rsqrtf((float)c1 + 1.0f); }
        if (base + 2 < n) { g_ptr[base+2] = p2; g_cursor[base+2] = p2; g_deg[base+2] = rsqrtf((float)c2 + 1.0f); }
        if (base + 3 < n) { g_ptr[base+3] = p3; g_cursor[base+3] = p3; g_deg[base+3] = rsqrtf((float)c3 + 1.0f); }
    }
}

// ---------------- CSR fill (4 edges/thread, full grid) ----------------
__global__ void __launch_bounds__(256) k_fill(const void* __restrict__ eidx, int E,
                                              long long nlim) {
    __shared__ int sf;
    int idx32 = block_detect_idx32(eidx, E, nlim, &sf);
    int base = (blockIdx.x * blockDim.x + threadIdx.x) * 4;
#pragma unroll
    for (int k = 0; k < 4; k++) {
        int e = base + k;
        if (e >= E) break;
        int src, dst;
        if (idx32) {
            const int* p = (const int*)eidx;
            src = p[e]; dst = p[E + e];
        } else {
            const long long* p = (const long long*)eidx;
            src = (int)p[e]; dst = (int)p[E + e];
        }
        int pos = atomicAdd(&g_cursor[dst], 1);
        g_csr_src[pos] = src;
    }
}

// ---------------- fused pre-MLP + layer GEMM: hws = ((x@W1+b1)@W2)*isq --------------
// 256 thr / 8 warps / 128 rows per block. Dynamic SMEM 64512B:
//   [0,36864)  region0: phase1 = W1s(18432)+As(18432); later Es (fp32 epilogues)
//   [36864,55296) C1 (fp16, ld 72)
//   [55296,64512) W2s (fp16, ld 72)
__global__ void __launch_bounds__(256) k_gemm0(const float* __restrict__ x,
                                               const float* __restrict__ W1,
                                               const float* __restrict__ b1,
                                               const float* __restrict__ W2,
                                               const int* __restrict__ cnt,
                                               __half* __restrict__ out, int n) {
    extern __shared__ __align__(16) char sm[];
    __half* W1s = (__half*)sm;                       // 128 x 64, ld 72
    __half* As  = (__half*)sm + 128 * 72;            // 128 x 64, ld 72
    float*  Es  = (float*)sm;                        // 8 x 16 x 72 fp32
    __half* C1  = (__half*)(sm + 36864);             // 128 x 64, ld 72
    __half* W2s = (__half*)(sm + 36864 + 18432);     // 64 x 64, ld 72

    int tid = threadIdx.x;
    int warpId = tid >> 5, lane = tid & 31;
    int nodeBase = blockIdx.x * 128;

    for (int i = tid; i < 128 * 64; i += 256) {
        int r = i >> 6, c = i & 63;
        W1s[r * 72 + c] = __float2half(W1[i]);
    }
    for (int i = tid; i < 64 * 64; i += 256) {
        int r = i >> 6, c = i & 63;
        W2s[r * 72 + c] = __float2half(W2[i]);
    }

    wmma::fragment<wmma::accumulator, 16, 16, 16, float> cf[4];
#pragma unroll
    for (int t = 0; t < 4; t++) wmma::fill_fragment(cf[t], 0.0f);

    int srow = tid >> 1;
    int scol = (tid & 1) * 32;
    int sgn = nodeBase + srow;
    bool sok = (sgn < n);
    const float* aptr = x + (size_t)sgn * 128 + scol;

    // ---- phase 1: C = x @ W1 (K=128 in two 64-col chunks) ----
#pragma unroll
    for (int c = 0; c < 2; c++) {
        __syncthreads();
#pragma unroll
        for (int q = 0; q < 4; q++) {
            float4 f0, f1;
            if (sok) {
                f0 = *(const float4*)(aptr + c * 64 + q * 8);
                f1 = *(const float4*)(aptr + c * 64 + q * 8 + 4);
            } else {
                f0 = make_float4(0.f, 0.f, 0.f, 0.f);
                f1 = f0;
            }
            __align__(16) __half2 hs[4];
            hs[0] = __floats2half2_rn(f0.x, f0.y);
            hs[1] = __floats2half2_rn(f0.z, f0.w);
            hs[2] = __floats2half2_rn(f1.x, f1.y);
            hs[3] = __floats2half2_rn(f1.z, f1.w);
            *(uint4*)(As + srow * 72 + scol + q * 8) = *(const uint4*)hs;
        }
        __syncthreads();
#pragma unroll
        for (int kk = 0; kk < 64; kk += 16) {
            wmma::fragment<wmma::matrix_a, 16, 16, 16, __half, wmma::row_major> af;
            wmma::load_matrix_sync(af, As + warpId * 16 * 72 + kk, 72);
#pragma unroll
            for (int t = 0; t < 4; t++) {
                wmma::fragment<wmma::matrix_b, 16, 16, 16, __half, wmma::row_major> bf;
                wmma::load_matrix_sync(bf, W1s + (c * 64 + kk) * 72 + t * 16, 72);
                wmma::mma_sync(cf[t], af, bf, cf[t]);
            }
        }
    }

    // ---- phase 2: fragments -> Es (fp32), overwrite W1s/As ----
    __syncthreads();
#pragma unroll
    for (int t = 0; t < 4; t++)
        wmma::store_matrix_sync(Es + warpId * 16 * 72 + t * 16, cf[t], 72,
                                wmma::mem_row_major);
    __syncthreads();

    // ---- phase 3: +b1, cvt fp16 -> C1 ----
    {
        const float* src = Es + srow * 72 + scol;
#pragma unroll
        for (int q = 0; q < 4; q++) {
            float4 va = *(const float4*)(src + q * 8);
            float4 vb = *(const float4*)(src + q * 8 + 4);
            float4 ba = *(const float4*)(b1 + scol + q * 8);
            float4 bc = *(const float4*)(b1 + scol + q * 8 + 4);
            __align__(16) __half2 hs[4];
            hs[0] = __floats2half2_rn(va.x + ba.x, va.y + ba.y);
            hs[1] = __floats2half2_rn(va.z + ba.z, va.w + ba.w);
            hs[2] = __floats2half2_rn(vb.x + bc.x, vb.y + bc.y);
            hs[3] = __floats2half2_rn(vb.z + bc.z, vb.w + bc.w);
            *(uint4*)(C1 + srow * 72 + scol + q * 8) = *(const uint4*)hs;
        }
    }
    __syncthreads();

    // ---- phase 4: D = C1 @ W2 (K=64) ----
    wmma::fragment<wmma::accumulator, 16, 16, 16, float> cg[4];
#pragma unroll
    for (int t = 0; t < 4; t++) wmma::fill_fragment(cg[t], 0.0f);
#pragma unroll
    for (int kk = 0; kk < 64; kk += 16) {
        wmma::fragment<wmma::matrix_a, 16, 16, 16, __half, wmma::row_major> af;
        wmma::load_matrix_sync(af, C1 + warpId * 16 * 72 + kk, 72);
#pragma unroll
        for (int t = 0; t < 4; t++) {
            wmma::fragment<wmma::matrix_b, 16, 16, 16, __half, wmma::row_major> bf;
            wmma::load_matrix_sync(bf, W2s + kk * 72 + t * 16, 72);
            wmma::mma_sync(cg[t], af, bf, cg[t]);
        }
    }
    __syncthreads();
#pragma unroll
    for (int t = 0; t < 4; t++)
        wmma::store_matrix_sync(Es + warpId * 16 * 72 + t * 16, cg[t], 72,
                                wmma::mem_row_major);
    __syncwarp();

    // ---- epilogue: *isq, fp16 out ----
    int erow = lane >> 1;
    int ecol = (lane & 1) * 32;
    int gn = nodeBase + warpId * 16 + erow;
    if (gn < n) {
        float s = rsqrtf((float)__ldg(&cnt[gn]) + 1.0f);
        const float* src = Es + warpId * 16 * 72 + erow * 72 + ecol;
        __half* o = out + (size_t)gn * 64 + ecol;
#pragma unroll
        for (int q = 0; q < 4; q++) {
            float4 va = *(const float4*)(src + q * 8);
            float4 vb = *(const float4*)(src + q * 8 + 4);
            __align__(16) __half2 p[4];
            p[0] = __floats2half2_rn(va.x * s, va.y * s);
            p[1] = __floats2half2_rn(va.z * s, va.w * s);
            p[2] = __floats2half2_rn(vb.x * s, vb.y * s);
            p[3] = __floats2half2_rn(vb.z * s, vb.w * s);
            *(uint4*)(o + q * 8) = *(const uint4*)p;
        }
    }
}

// ---------------- layer-2 GEMM: hws = (h1 @ W)*isq, fp16 in/out, K=64 ----------------
__global__ void __launch_bounds__(256) k_gemm_h(const __half* __restrict__ A,
                                                const float* __restrict__ W,
                                                const int* __restrict__ cnt,
                                                __half* __restrict__ out, int n) {
    __shared__ __align__(16) char smbuf[36864];
    __half* Ws = (__half*)smbuf;              // 64 x 64, ld 72 (9216B)
    __half* As = (__half*)smbuf + 64 * 72;    // 128 x 64, ld 72 (18432B)
    float*  Es = (float*)smbuf;               // epilogue (36864B)

    int tid = threadIdx.x;
    int warpId = tid >> 5, lane = tid & 31;
    int nodeBase = blockIdx.x * 128;

    for (int i = tid; i < 64 * 64; i += 256) {
        int r = i >> 6, c = i & 63;
        Ws[r * 72 + c] = __float2half(W[i]);
    }

    int srow = tid >> 1;
    int scol = (tid & 1) * 32;
    int sgn = nodeBase + srow;
    if (sgn < n) {
        const uint4* ap = (const uint4*)(A + (size_t)sgn * 64 + scol);
        uint4* dp = (uint4*)(As + srow * 72 + scol);
        dp[0] = __ldg(&ap[0]); dp[1] = __ldg(&ap[1]);
        dp[2] = __ldg(&ap[2]); dp[3] = __ldg(&ap[3]);
    } else {
        uint4 z = make_uint4(0u, 0u, 0u, 0u);
        uint4* dp = (uint4*)(As + srow * 72 + scol);
        dp[0] = z; dp[1] = z; dp[2] = z; dp[3] = z;
    }
    __syncthreads();

    wmma::fragment<wmma::accumulator, 16, 16, 16, float> cf[4];
#pragma unroll
    for (int t = 0; t < 4; t++) wmma::fill_fragment(cf[t], 0.0f);
#pragma unroll
    for (int kk = 0; kk < 64; kk += 16) {
        wmma::fragment<wmma::matrix_a, 16, 16, 16, __half, wmma::row_major> af;
        wmma::load_matrix_sync(af, As + warpId * 16 * 72 + kk, 72);
#pragma unroll
        for (int t = 0; t < 4; t++) {
            wmma::fragment<wmma::matrix_b, 16, 16, 16, __half, wmma::row_major> bf;
            wmma::load_matrix_sync(bf, Ws + kk * 72 + t * 16, 72);
            wmma::mma_sync(cf[t], af, bf, cf[t]);
        }
    }
    __syncthreads();
#pragma unroll
    for (int t = 0; t < 4; t++)
        wmma::store_matrix_sync(Es + warpId * 16 * 72 + t * 16, cf[t], 72,
                                wmma::mem_row_major);
    __syncwarp();

    int erow = lane >> 1;
    int ecol = (lane & 1) * 32;
    int gn = nodeBase + warpId * 16 + erow;
    if (gn < n) {
        float s = rsqrtf((float)__ldg(&cnt[gn]) + 1.0f);
        const float* src = Es + warpId * 16 * 72 + erow * 72 + ecol;
        __half* o = out + (size_t)gn * 64 + ecol;
#pragma unroll
        for (int q = 0; q < 4; q++) {
            float4 va = *(const float4*)(src + q * 8);
            float4 vb = *(const float4*)(src + q * 8 + 4);
            __align__(16) __half2 p[4];
            p[0] = __floats2half2_rn(va.x * s, va.y * s);
            p[1] = __floats2half2_rn(va.z * s, va.w * s);
            p[2] = __floats2half2_rn(vb.x * s, vb.y * s);
            p[3] = __floats2half2_rn(vb.z * s, vb.w * s);
            *(uint4*)(o + q * 8) = *(const uint4*)p;
        }
    }
}

// ---------------- fused gather + self + bias + LN + ReLU (+skip+readout) -------------
// 4 independent nodes per warp, 8 lanes x uint4 per row. h1 output/skip in fp16.
__global__ void __launch_bounds__(256) k_gather(const float* __restrict__ bias,
                                                const float* __restrict__ lng,
                                                const float* __restrict__ lnb,
                                                __half* __restrict__ outh, int n,
                                                int do_readout,
                                                const void* __restrict__ batch) {
    const unsigned FULL = 0xffffffffu;
    int t = blockIdx.x * blockDim.x + threadIdx.x;
    int node = t >> 3;
    int lane = threadIdx.x & 31;
    int grp = lane >> 3, sub = lane & 7;
    bool ok = (node < n);
    int nodec = ok ? node : (n - 1);

    int start = g_ptr[nodec];
    int cnt   = ok ? g_cnt[nodec] : 0;

    int mmax = cnt;
    mmax = max(mmax, __shfl_xor_sync(FULL, mmax, 8));
    mmax = max(mmax, __shfl_xor_sync(FULL, mmax, 16));

    const uint4* hw4 = (const uint4*)g_hws;
    __half2 acc[4];
    __half2 z = __float2half2_rn(0.f);
#pragma unroll
    for (int k = 0; k < 4; k++) acc[k] = z;

    for (int done = 0; done < mmax; done += 8) {
        int b = 0;
        if (done + sub < cnt) b = __ldg(&g_csr_src[start + done + sub]);
        int lim = cnt - done;
        uint4 v[8];
#pragma unroll
        for (int j = 0; j < 8; j++) {
            int s = __shfl_sync(FULL, b, (grp << 3) + j);
            v[j] = make_uint4(0u, 0u, 0u, 0u);
            if (j < lim) v[j] = __ldg(&hw4[(size_t)s * 8 + sub]);
        }
#pragma unroll
        for (int j = 0; j < 8; j++) {
            const __half2* p = (const __half2*)&v[j];
            acc[0] = __hadd2(acc[0], p[0]);
            acc[1] = __hadd2(acc[1], p[1]);
            acc[2] = __hadd2(acc[2], p[2]);
            acc[3] = __hadd2(acc[3], p[3]);
        }
    }

    uint4 sv = __ldg(&hw4[(size_t)nodec * 8 + sub]);
    const __half2* ps = (const __half2*)&sv;
    float isqn = g_deg[nodec];
    const float4* b4 = (const float4*)bias;
    float4 bl = __ldg(&b4[sub * 2]), bh = __ldg(&b4[sub * 2 + 1]);
    float bb[8] = {bl.x, bl.y, bl.z, bl.w, bh.x, bh.y, bh.z, bh.w};

    float v8[8];
#pragma unroll
    for (int k = 0; k < 4; k++) {
        float2 f  = __half22float2(acc[k]);
        float2 fs = __half22float2(ps[k]);
        v8[2 * k]     = fmaf(isqn, f.x + fs.x, bb[2 * k]);
        v8[2 * k + 1] = fmaf(isqn, f.y + fs.y, bb[2 * k + 1]);
    }

    float sum = 0.f;
#pragma unroll
    for (int i = 0; i < 8; i++) sum += v8[i];
#pragma unroll
    for (int o = 4; o; o >>= 1) sum += __shfl_xor_sync(FULL, sum, o);
    float mu = sum * (1.0f / 64.0f);

    float var = 0.f, d8[8];
#pragma unroll
    for (int i = 0; i < 8; i++) { d8[i] = v8[i] - mu; var += d8[i] * d8[i]; }
#pragma unroll
    for (int o = 4; o; o >>= 1) var += __shfl_xor_sync(FULL, var, o);
    float rstd = rsqrtf(var * (1.0f / 64.0f) + 1e-5f);

    const float4* g4 = (const float4*)lng;
    const float4* l4 = (const float4*)lnb;
    float4 gl = __ldg(&g4[sub * 2]), gh = __ldg(&g4[sub * 2 + 1]);
    float4 ll = __ldg(&l4[sub * 2]), lh = __ldg(&l4[sub * 2 + 1]);
    float gg[8] = {gl.x, gl.y, gl.z, gl.w, gh.x, gh.y, gh.z, gh.w};
    float lb[8] = {ll.x, ll.y, ll.z, ll.w, lh.x, lh.y, lh.z, lh.w};

    float o8[8];
#pragma unroll
    for (int i = 0; i < 8; i++)
        o8[i] = fmaxf(fmaf(d8[i] * rstd, gg[i], lb[i]), 0.f);

    if (!ok) return;
    if (!do_readout) {
        __align__(16) __half2 p[4];
        p[0] = __floats2half2_rn(o8[0], o8[1]);
        p[1] = __floats2half2_rn(o8[2], o8[3]);
        p[2] = __floats2half2_rn(o8[4], o8[5]);
        p[3] = __floats2half2_rn(o8[6], o8[7]);
        *(uint4*)(outh + (size_t)node * 64 + sub * 8) = *(const uint4*)p;
    } else {
        uint4 hv = __ldg((const uint4*)(g_h1 + (size_t)node * 64 + sub * 8));
        const __half2* ph = (const __half2*)&hv;
        float h8[8];
#pragma unroll
        for (int k = 0; k < 4; k++) {
            float2 f = __half22float2(ph[k]);
            h8[2 * k] = f.x; h8[2 * k + 1] = f.y;
        }
        int grpi = g_idx32 ? ((const int*)batch)[node]
                           : (int)((const long long*)batch)[node];
        float4* r4 = (float4*)(g_readout + (size_t)grpi * 64 + sub * 8);
        atomicAdd(&r4[0], make_float4(o8[0] + h8[0], o8[1] + h8[1], o8[2] + h8[2], o8[3] + h8[3]));
        atomicAdd(&r4[1], make_float4(o8[4] + h8[4], o8[5] + h8[5], o8[6] + h8[6], o8[7] + h8[7]));
    }
}

// ---------------- post GEMM ----------------
__global__ void k_post(const float* __restrict__ W, const float* __restrict__ b,
                       float* __restrict__ out, int G) {
    __shared__ float r[64];
    int g = blockIdx.x;
    r[threadIdx.x] = g_readout[(size_t)g * 64 + threadIdx.x];
    __syncthreads();
    int c = threadIdx.x;
    if (c < 40) {
        float acc = b[c];
#pragma unroll
        for (int k = 0; k < 64; k++) acc = fmaf(r[k], __ldg(&W[k * 40 + c]), acc);
        out[(size_t)g * 40 + c] = acc;
    }
}

// ---------------- launch ----------------
extern "C" void kernel_launch(void* const* d_in, const int* in_sizes, int n_in,
                              void* d_out, int out_size) {
    const float* x      = (const float*)d_in[0];
    const void*  eidx   = d_in[1];
    const void*  batch  = d_in[2];
    const float* pre_w  = (const float*)d_in[3];
    const float* pre_b  = (const float*)d_in[4];
    const float* c1_w   = (const float*)d_in[5];
    const float* c1_b   = (const float*)d_in[6];
    const float* n1_g   = (const float*)d_in[7];
    const float* n1_b   = (const float*)d_in[8];
    const float* c2_w   = (const float*)d_in[9];
    const float* c2_b   = (const float*)d_in[10];
    const float* n2_g   = (const float*)d_in[11];
    const float* n2_b   = (const float*)d_in[12];
    const float* post_w = (const float*)d_in[13];
    const float* post_b = (const float*)d_in[14];

    int N = in_sizes[0] / 128;
    int E = in_sizes[1] / 2;
    int G = out_size / 40;

    float* p_readout;
    __half *p_hws, *p_h1;
    int *p_cnt, *p_flag;
    cudaGetSymbolAddress((void**)&p_hws,     g_hws);
    cudaGetSymbolAddress((void**)&p_h1,      g_h1);
    cudaGetSymbolAddress((void**)&p_cnt,     g_cnt);
    cudaGetSymbolAddress((void**)&p_flag,    g_scanflag);
    cudaGetSymbolAddress((void**)&p_readout, g_readout);

    static cudaStream_t s1 = nullptr, s2 = nullptr;
    static cudaEvent_t evFork = nullptr, evHist = nullptr, evG1 = nullptr, evCsr = nullptr;
    if (!s1) {
        cudaStreamCreateWithFlags(&s1, cudaStreamNonBlocking);
        cudaStreamCreateWithFlags(&s2, cudaStreamNonBlocking);
        cudaEventCreateWithFlags(&evFork, cudaEventDisableTiming);
        cudaEventCreateWithFlags(&evHist, cudaEventDisableTiming);
        cudaEventCreateWithFlags(&evG1,   cudaEventDisableTiming);
        cudaEventCreateWithFlags(&evCsr,  cudaEventDisableTiming);
        cudaFuncSetAttribute(k_gemm0, cudaFuncAttributeMaxDynamicSharedMemorySize, 65536);
    }

    cudaEventRecord(evFork, 0);
    cudaStreamWaitEvent(s1, evFork, 0);
    cudaStreamWaitEvent(s2, evFork, 0);

    // --- s2: memsets + CSR build ---
    cudaMemsetAsync(p_cnt, 0, (size_t)N * 4, s2);
    cudaMemsetAsync(p_flag, 0, 128 * 4, s2);
    cudaMemsetAsync(p_readout, 0, (size_t)G * 64 * 4, s2);
    k_hist<<<(E + 1023) / 1024, 256, 0, s2>>>(eidx, E, (long long)N);
    cudaEventRecord(evHist, s2);
    k_scan<<<(N + 1023) / 1024, 256, 0, s2>>>(N);
    k_fill<<<(E + 1023) / 1024, 256, 0, s2>>>(eidx, E, (long long)N);
    cudaEventRecord(evCsr, s2);

    // --- s1: fused pre-MLP + layer-1 GEMM (needs only hist counts) ---
    cudaStreamWaitEvent(s1, evHist, 0);
    k_gemm0<<<(N + 127) / 128, 256, 64512, s1>>>(x, pre_w, pre_b, c1_w, p_cnt, p_hws, N);
    cudaEventRecord(evG1, s1);

    // --- join ---
    cudaStreamWaitEvent(0, evG1, 0);
    cudaStreamWaitEvent(0, evCsr, 0);

    // layer 1 gather -> h1 (fp16)
    k_gather<<<((size_t)N * 8 + 255) / 256, 256>>>(c1_b, n1_g, n1_b, p_h1, N, 0, nullptr);

    // layer 2
    k_gemm_h<<<(N + 127) / 128, 256>>>(p_h1, c2_w, p_cnt, p_hws, N);
    k_gather<<<((size_t)N * 8 + 255) / 256, 256>>>(c2_b, n2_g, n2_b, nullptr, N, 1, batch);

    // post
    k_post<<<G, 64>>>(post_w, post_b, (float*)d_out, G);
}

// round 13
// speedup vs baseline: 1.8679x; 1.0242x over previous
#include <cuda_runtime.h>
#include <cuda_fp16.h>
#include <mma.h>
#include <cstdint>
#include <cstddef>

using namespace nvcuda;

// Problem constants: N=100000, E=1600000, F=128, H=64, C=40, G=2048
#define NMAX 100000
#define EMAX 1600000
#define GMAX 2048

// ---------------- scratch (device globals; no runtime alloc allowed) ----------------
__device__ __align__(128) __half g_hws[NMAX * 64];  // (h @ W) * isq (fp16) per layer
__device__ __align__(128) __half g_h1 [NMAX * 64];  // layer-1 activations (fp16)
__device__ __align__(16)  float  g_deg[NMAX];       // isq
__device__ __align__(128) float  g_readout[GMAX * 64];
__device__ __align__(16)  int    g_cnt[NMAX];       // per-dst degree
__device__ __align__(16)  int    g_ptr[NMAX];       // CSR row starts
__device__ __align__(16)  int    g_cursor[NMAX];    // fill cursors
__device__ __align__(16)  int    g_csr_src[EMAX];   // CSR column (src) indices
__device__ int g_scanflag[128];                     // lookback published aggregates (+1)
__device__ int g_idx32;                             // 1 if indices are int32

// ---------------- per-block index-dtype detection ----------------
__device__ __forceinline__ int block_detect_idx32(const void* e, int E, long long nlim,
                                                  int* s_flag) {
    if (threadIdx.x == 0) *s_flag = 0;
    __syncthreads();
    int m = E < 64 ? E : 64;
    if ((int)threadIdx.x < m) {
        long long v = ((const long long*)e)[threadIdx.x];
        if (v < 0 || v >= nlim) *s_flag = 1;
    }
    __syncthreads();
    return *s_flag;
}

// ---------------- degree histogram (4 edges/thread; block 0 publishes g_idx32) -------
__global__ void __launch_bounds__(256) k_hist(const void* __restrict__ eidx, int E,
                                              long long nlim) {
    __shared__ int sf;
    int idx32 = block_detect_idx32(eidx, E, nlim, &sf);
    if (blockIdx.x == 0 && threadIdx.x == 0) g_idx32 = idx32;
    int base = (blockIdx.x * blockDim.x + threadIdx.x) * 4;
    if (idx32) {
        const int* d = (const int*)eidx + E;
#pragma unroll
        for (int k = 0; k < 4; k++) {
            int e = base + k;
            if (e < E) atomicAdd(&g_cnt[d[e]], 1);
        }
    } else {
        const long long* d = (const long long*)eidx + E;
#pragma unroll
        for (int k = 0; k < 4; k++) {
            int e = base + k;
            if (e < E) atomicAdd(&g_cnt[(int)d[e]], 1);
        }
    }
}

// ---------------- single-pass exclusive scan (lookback) + cursor + isq ----------------
__global__ void __launch_bounds__(256) k_scan(int n) {
    __shared__ int wsum[8];
    __shared__ int red[8];
    __shared__ int s_prefix;
    int bid = blockIdx.x;
    int base = bid * 1024 + threadIdx.x * 4;

    int c0 = 0, c1 = 0, c2 = 0, c3 = 0;
    if (base + 3 < n) {
        int4 c = *(const int4*)&g_cnt[base];
        c0 = c.x; c1 = c.y; c2 = c.z; c3 = c.w;
    } else if (base < n) {
        c0 = g_cnt[base];
        if (base + 1 < n) c1 = g_cnt[base + 1];
        if (base + 2 < n) c2 = g_cnt[base + 2];
    }
    int tot = c0 + c1 + c2 + c3;
    int lane = threadIdx.x & 31, wid = threadIdx.x >> 5;
    int v = tot;
#pragma unroll
    for (int o = 1; o < 32; o <<= 1) {
        int u = __shfl_up_sync(0xffffffffu, v, o);
        if (lane >= o) v += u;
    }
    if (lane == 31) wsum[wid] = v;
    __syncthreads();
    if (threadIdx.x == 0) {
        int s = 0;
        for (int i = 0; i < 8; i++) { int t = wsum[i]; wsum[i] = s; s += t; }
        atomicExch(&g_scanflag[bid], s + 1);
    }
    __syncthreads();

    int part = 0;
    if ((int)threadIdx.x < bid) {
        volatile int* f = &g_scanflag[threadIdx.x];
        int x;
        do { x = *f; } while (x == 0);
        part = x - 1;
    }
#pragma unroll
    for (int o = 16; o; o >>= 1) part += __shfl_xor_sync(0xffffffffu, part, o);
    if (lane == 0) red[wid] = part;
    __syncthreads();
    if (threadIdx.x == 0) {
        int s = 0;
        for (int i = 0; i < 8; i++) s += red[i];
        s_prefix = s;
    }
    __syncthreads();

    int excl = v - tot + wsum[wid] + s_prefix;
    if (base < n) {
        int p0 = excl, p1 = p0 + c0, p2 = p1 + c1, p3 = p2 + c2;
        g_ptr[base] = p0; g_cursor[base] = p0; g_deg[base] = rsqrtf((float)c0 + 1.0f);
        if (base + 1 < n) { g_ptr[base+1] = p1; g_cursor[base+1] = p1; g_deg[base+1] = rsqrtf((float)c1 + 1.0f); }
        if (base + 2 < n) { g_ptr[base+2] = p2; g_cursor[base+2] = p2; g_deg[base+2] = rsqrtf((float)c2 + 1.0f); }
        if (base + 3 < n) { g_ptr[base+3] = p3; g_cursor[base+3] = p3; g_deg[base+3] = rsqrtf((float)c3 + 1.0f); }
    }
}

// ---------------- CSR fill (4 edges/thread, full grid) ----------------
__global__ void __launch_bounds__(256) k_fill(const void* __restrict__ eidx, int E,
                                              long long nlim) {
    __shared__ int sf;
    int idx32 = block_detect_idx32(eidx, E, nlim, &sf);
    int base = (blockIdx.x * blockDim.x + threadIdx.x) * 4;
#pragma unroll
    for (int k = 0; k < 4; k++) {
        int e = base + k;
        if (e >= E) break;
        int src, dst;
        if (idx32) {
            const int* p = (const int*)eidx;
            src = p[e]; dst = p[E + e];
        } else {
            const long long* p = (const long long*)eidx;
            src = (int)p[e]; dst = (int)p[E + e];
        }
        int pos = atomicAdd(&g_cursor[dst], 1);
        g_csr_src[pos] = src;
    }
}

// ---------------- fused pre-MLP + layer GEMM, warp-local phases, 1 block barrier -----
// hws = ((x@W1+b1)@W2)*isq. 256 thr / 8 warps / 128 rows per block.
// Dynamic SMEM 64512B: W1s[0,18432) W2s[18432,27648) As[27648,46080) C1[46080,64512)
// Per-warp strips (16 rows, ld 72). fp32 tmp (16x20) aliases warp's own dead A strip.
__global__ void __launch_bounds__(256) k_gemm0(const float* __restrict__ x,
                                               const float* __restrict__ W1,
                                               const float* __restrict__ b1,
                                               const float* __restrict__ W2,
                                               const int* __restrict__ cnt,
                                               __half* __restrict__ out, int n) {
    extern __shared__ __align__(16) char sm[];
    __half* W1s = (__half*)sm;                       // 128 x 64, ld 72
    __half* W2s = (__half*)(sm + 18432);             // 64 x 64, ld 72
    __half* As  = (__half*)(sm + 27648);             // 128 x 64, ld 72 (warp strips)
    __half* C1  = (__half*)(sm + 46080);             // 128 x 64, ld 72 (warp strips)

    int tid = threadIdx.x;
    int warpId = tid >> 5, lane = tid & 31;
    int nodeBase = blockIdx.x * 128;

    for (int i = tid; i < 128 * 64; i += 256) {
        int r = i >> 6, c = i & 63;
        W1s[r * 72 + c] = __float2half(W1[i]);
    }
    for (int i = tid; i < 64 * 64; i += 256) {
        int r = i >> 6, c = i & 63;
        W2s[r * 72 + c] = __float2half(W2[i]);
    }
    __syncthreads();   // the ONLY block barrier

    __half* Aw  = As + warpId * 1152;   // warp strip: 16 x 72 halfs
    __half* C1w = C1 + warpId * 1152;
    float*  tmpf = (float*)Aw;          // 16 x 20 fp32 aliased (used after A dead)

    int srow = tid >> 1;                // global staging row (warp-aligned)
    int wrow = srow & 15;               // row within warp strip
    int scol = (tid & 1) * 32;
    int sgn = nodeBase + srow;
    bool sok = (sgn < n);
    const float* aptr = x + (size_t)sgn * 128 + scol;

    // ---- phase 1: C = x @ W1 (K=128, two 64-col chunks), warp-local ----
    wmma::fragment<wmma::accumulator, 16, 16, 16, float> cf[4];
#pragma unroll
    for (int t = 0; t < 4; t++) wmma::fill_fragment(cf[t], 0.0f);

#pragma unroll
    for (int c = 0; c < 2; c++) {
        __syncwarp();
#pragma unroll
        for (int q = 0; q < 4; q++) {
            float4 f0, f1;
            if (sok) {
                f0 = *(const float4*)(aptr + c * 64 + q * 8);
                f1 = *(const float4*)(aptr + c * 64 + q * 8 + 4);
            } else {
                f0 = make_float4(0.f, 0.f, 0.f, 0.f);
                f1 = f0;
            }
            __align__(16) __half2 hs[4];
            hs[0] = __floats2half2_rn(f0.x, f0.y);
            hs[1] = __floats2half2_rn(f0.z, f0.w);
            hs[2] = __floats2half2_rn(f1.x, f1.y);
            hs[3] = __floats2half2_rn(f1.z, f1.w);
            *(uint4*)(Aw + wrow * 72 + scol + q * 8) = *(const uint4*)hs;
        }
        __syncwarp();
#pragma unroll
        for (int kk = 0; kk < 64; kk += 16) {
            wmma::fragment<wmma::matrix_a, 16, 16, 16, __half, wmma::row_major> af;
            wmma::load_matrix_sync(af, Aw + kk, 72);
#pragma unroll
            for (int t = 0; t < 4; t++) {
                wmma::fragment<wmma::matrix_b, 16, 16, 16, __half, wmma::row_major> bf;
                wmma::load_matrix_sync(bf, W1s + (c * 64 + kk) * 72 + t * 16, 72);
                wmma::mma_sync(cf[t], af, bf, cf[t]);
            }
        }
    }

    // ---- phase 2: cf -> (+b1) -> fp16 C1, warp-local via 16x20 tmp ----
    int tr = lane >> 1;
    int tc = (lane & 1) * 8;
#pragma unroll
    for (int t = 0; t < 4; t++) {
        __syncwarp();
        wmma::store_matrix_sync(tmpf, cf[t], 20, wmma::mem_row_major);
        __syncwarp();
        const float* s = tmpf + tr * 20 + tc;
        float4 v0 = *(const float4*)s;
        float4 v1 = *(const float4*)(s + 4);
        float4 ba = *(const float4*)(b1 + t * 16 + tc);
        float4 bb = *(const float4*)(b1 + t * 16 + tc + 4);
        __align__(16) __half2 hs[4];
        hs[0] = __floats2half2_rn(v0.x + ba.x, v0.y + ba.y);
        hs[1] = __floats2half2_rn(v0.z + ba.z, v0.w + ba.w);
        hs[2] = __floats2half2_rn(v1.x + bb.x, v1.y + bb.y);
        hs[3] = __floats2half2_rn(v1.z + bb.z, v1.w + bb.w);
        __syncwarp();
        *(uint4*)(C1w + tr * 72 + t * 16 + tc) = *(const uint4*)hs;
    }
    __syncwarp();

    // ---- phase 3: D = C1 @ W2 (K=64), warp-local ----
    wmma::fragment<wmma::accumulator, 16, 16, 16, float> cg[4];
#pragma unroll
    for (int t = 0; t < 4; t++) wmma::fill_fragment(cg[t], 0.0f);
#pragma unroll
    for (int kk = 0; kk < 64; kk += 16) {
        wmma::fragment<wmma::matrix_a, 16, 16, 16, __half, wmma::row_major> af;
        wmma::load_matrix_sync(af, C1w + kk, 72);
#pragma unroll
        for (int t = 0; t < 4; t++) {
            wmma::fragment<wmma::matrix_b, 16, 16, 16, __half, wmma::row_major> bf;
            wmma::load_matrix_sync(bf, W2s + kk * 72 + t * 16, 72);
            wmma::mma_sync(cg[t], af, bf, cg[t]);
        }
    }

    // ---- epilogue: *isq, fp16 out, warp-local via tmp ----
    int gn = nodeBase + warpId * 16 + tr;
    float siq = (gn < n) ? rsqrtf((float)__ldg(&cnt[gn]) + 1.0f) : 0.f;
#pragma unroll
    for (int t = 0; t < 4; t++) {
        __syncwarp();
        wmma::store_matrix_sync(tmpf, cg[t], 20, wmma::mem_row_major);
        __syncwarp();
        if (gn < n) {
            const float* s = tmpf + tr * 20 + tc;
            float4 v0 = *(const float4*)s;
            float4 v1 = *(const float4*)(s + 4);
            __align__(16) __half2 p[4];
            p[0] = __floats2half2_rn(v0.x * siq, v0.y * siq);
            p[1] = __floats2half2_rn(v0.z * siq, v0.w * siq);
            p[2] = __floats2half2_rn(v1.x * siq, v1.y * siq);
            p[3] = __floats2half2_rn(v1.z * siq, v1.w * siq);
            *(uint4*)(out + (size_t)gn * 64 + t * 16 + tc) = *(const uint4*)p;
        }
    }
}

// ---------------- layer-2 GEMM: hws = (h1 @ W)*isq, fp16 in/out, 1 block barrier -----
__global__ void __launch_bounds__(256) k_gemm_h(const __half* __restrict__ A,
                                                const float* __restrict__ W,
                                                const int* __restrict__ cnt,
                                                __half* __restrict__ out, int n) {
    __shared__ __align__(16) __half Ws[64 * 72];
    __shared__ __align__(16) __half As[128 * 72];

    int tid = threadIdx.x;
    int warpId = tid >> 5, lane = tid & 31;
    int nodeBase = blockIdx.x * 128;

    for (int i = tid; i < 64 * 64; i += 256) {
        int r = i >> 6, c = i & 63;
        Ws[r * 72 + c] = __float2half(W[i]);
    }
    __syncthreads();   // only block barrier

    __half* Aw = As + warpId * 1152;
    float* tmpf = (float*)Aw;

    int srow = tid >> 1;
    int wrow = srow & 15;
    int scol = (tid & 1) * 32;
    int sgn = nodeBase + srow;
    if (sgn < n) {
        const uint4* ap = (const uint4*)(A + (size_t)sgn * 64 + scol);
        uint4* dp = (uint4*)(Aw + wrow * 72 + scol);
        dp[0] = __ldg(&ap[0]); dp[1] = __ldg(&ap[1]);
        dp[2] = __ldg(&ap[2]); dp[3] = __ldg(&ap[3]);
    } else {
        uint4 z = make_uint4(0u, 0u, 0u, 0u);
        uint4* dp = (uint4*)(Aw + wrow * 72 + scol);
        dp[0] = z; dp[1] = z; dp[2] = z; dp[3] = z;
    }
    __syncwarp();

    wmma::fragment<wmma::accumulator, 16, 16, 16, float> cf[4];
#pragma unroll
    for (int t = 0; t < 4; t++) wmma::fill_fragment(cf[t], 0.0f);
#pragma unroll
    for (int kk = 0; kk < 64; kk += 16) {
        wmma::fragment<wmma::matrix_a, 16, 16, 16, __half, wmma::row_major> af;
        wmma::load_matrix_sync(af, Aw + kk, 72);
#pragma unroll
        for (int t = 0; t < 4; t++) {
            wmma::fragment<wmma::matrix_b, 16, 16, 16, __half, wmma::row_major> bf;
            wmma::load_matrix_sync(bf, Ws + kk * 72 + t * 16, 72);
            wmma::mma_sync(cf[t], af, bf, cf[t]);
        }
    }

    int tr = lane >> 1;
    int tc = (lane & 1) * 8;
    int gn = nodeBase + warpId * 16 + tr;
    float siq = (gn < n) ? rsqrtf((float)__ldg(&cnt[gn]) + 1.0f) : 0.f;
#pragma unroll
    for (int t = 0; t < 4; t++) {
        __syncwarp();
        wmma::store_matrix_sync(tmpf, cf[t], 20, wmma::mem_row_major);
        __syncwarp();
        if (gn < n) {
            const float* s = tmpf + tr * 20 + tc;
            float4 v0 = *(const float4*)s;
            float4 v1 = *(const float4*)(s + 4);
            __align__(16) __half2 p[4];
            p[0] = __floats2half2_rn(v0.x * siq, v0.y * siq);
            p[1] = __floats2half2_rn(v0.z * siq, v0.w * siq);
            p[2] = __floats2half2_rn(v1.x * siq, v1.y * siq);
            p[3] = __floats2half2_rn(v1.z * siq, v1.w * siq);
            *(uint4*)(out + (size_t)gn * 64 + t * 16 + tc) = *(const uint4*)p;
        }
    }
}

// ---------------- fused gather + self + bias + LN + ReLU (+skip+readout) -------------
// 4 independent nodes per warp, 8 lanes x uint4 per row. h1 output/skip in fp16.
__global__ void __launch_bounds__(256) k_gather(const float* __restrict__ bias,
                                                const float* __restrict__ lng,
                                                const float* __restrict__ lnb,
                                                __half* __restrict__ outh, int n,
                                                int do_readout,
                                                const void* __restrict__ batch) {
    const unsigned FULL = 0xffffffffu;
    int t = blockIdx.x * blockDim.x + threadIdx.x;
    int node = t >> 3;
    int lane = threadIdx.x & 31;
    int grp = lane >> 3, sub = lane & 7;
    bool ok = (node < n);
    int nodec = ok ? node : (n - 1);

    int start = g_ptr[nodec];
    int cnt   = ok ? g_cnt[nodec] : 0;

    int mmax = cnt;
    mmax = max(mmax, __shfl_xor_sync(FULL, mmax, 8));
    mmax = max(mmax, __shfl_xor_sync(FULL, mmax, 16));

    const uint4* hw4 = (const uint4*)g_hws;
    __half2 acc[4];
    __half2 z = __float2half2_rn(0.f);
#pragma unroll
    for (int k = 0; k < 4; k++) acc[k] = z;

    for (int done = 0; done < mmax; done += 8) {
        int b = 0;
        if (done + sub < cnt) b = __ldg(&g_csr_src[start + done + sub]);
        int lim = cnt - done;
        uint4 v[8];
#pragma unroll
        for (int j = 0; j < 8; j++) {
            int s = __shfl_sync(FULL, b, (grp << 3) + j);
            v[j] = make_uint4(0u, 0u, 0u, 0u);
            if (j < lim) v[j] = __ldg(&hw4[(size_t)s * 8 + sub]);
        }
#pragma unroll
        for (int j = 0; j < 8; j++) {
            const __half2* p = (const __half2*)&v[j];
            acc[0] = __hadd2(acc[0], p[0]);
            acc[1] = __hadd2(acc[1], p[1]);
            acc[2] = __hadd2(acc[2], p[2]);
            acc[3] = __hadd2(acc[3], p[3]);
        }
    }

    uint4 sv = __ldg(&hw4[(size_t)nodec * 8 + sub]);
    const __half2* ps = (const __half2*)&sv;
    float isqn = g_deg[nodec];
    const float4* b4 = (const float4*)bias;
    float4 bl = __ldg(&b4[sub * 2]), bh = __ldg(&b4[sub * 2 + 1]);
    float bb[8] = {bl.x, bl.y, bl.z, bl.w, bh.x, bh.y, bh.z, bh.w};

    float v8[8];
#pragma unroll
    for (int k = 0; k < 4; k++) {
        float2 f  = __half22float2(acc[k]);
        float2 fs = __half22float2(ps[k]);
        v8[2 * k]     = fmaf(isqn, f.x + fs.x, bb[2 * k]);
        v8[2 * k + 1] = fmaf(isqn, f.y + fs.y, bb[2 * k + 1]);
    }

    float sum = 0.f;
#pragma unroll
    for (int i = 0; i < 8; i++) sum += v8[i];
#pragma unroll
    for (int o = 4; o; o >>= 1) sum += __shfl_xor_sync(FULL, sum, o);
    float mu = sum * (1.0f / 64.0f);

    float var = 0.f, d8[8];
#pragma unroll
    for (int i = 0; i < 8; i++) { d8[i] = v8[i] - mu; var += d8[i] * d8[i]; }
#pragma unroll
    for (int o = 4; o; o >>= 1) var += __shfl_xor_sync(FULL, var, o);
    float rstd = rsqrtf(var * (1.0f / 64.0f) + 1e-5f);

    const float4* g4 = (const float4*)lng;
    const float4* l4 = (const float4*)lnb;
    float4 gl = __ldg(&g4[sub * 2]), gh = __ldg(&g4[sub * 2 + 1]);
    float4 ll = __ldg(&l4[sub * 2]), lh = __ldg(&l4[sub * 2 + 1]);
    float gg[8] = {gl.x, gl.y, gl.z, gl.w, gh.x, gh.y, gh.z, gh.w};
    float lb[8] = {ll.x, ll.y, ll.z, ll.w, lh.x, lh.y, lh.z, lh.w};

    float o8[8];
#pragma unroll
    for (int i = 0; i < 8; i++)
        o8[i] = fmaxf(fmaf(d8[i] * rstd, gg[i], lb[i]), 0.f);

    if (!ok) return;
    if (!do_readout) {
        __align__(16) __half2 p[4];
        p[0] = __floats2half2_rn(o8[0], o8[1]);
        p[1] = __floats2half2_rn(o8[2], o8[3]);
        p[2] = __floats2half2_rn(o8[4], o8[5]);
        p[3] = __floats2half2_rn(o8[6], o8[7]);
        *(uint4*)(outh + (size_t)node * 64 + sub * 8) = *(const uint4*)p;
    } else {
        uint4 hv = __ldg((const uint4*)(g_h1 + (size_t)node * 64 + sub * 8));
        const __half2* ph = (const __half2*)&hv;
        float h8[8];
#pragma unroll
        for (int k = 0; k < 4; k++) {
            float2 f = __half22float2(ph[k]);
            h8[2 * k] = f.x; h8[2 * k + 1] = f.y;
        }
        int grpi = g_idx32 ? ((const int*)batch)[node]
                           : (int)((const long long*)batch)[node];
        float4* r4 = (float4*)(g_readout + (size_t)grpi * 64 + sub * 8);
        atomicAdd(&r4[0], make_float4(o8[0] + h8[0], o8[1] + h8[1], o8[2] + h8[2], o8[3] + h8[3]));
        atomicAdd(&r4[1], make_float4(o8[4] + h8[4], o8[5] + h8[5], o8[6] + h8[6], o8[7] + h8[7]));
    }
}

// ---------------- post GEMM ----------------
__global__ void k_post(const float* __restrict__ W, const float* __restrict__ b,
                       float* __restrict__ out, int G) {
    __shared__ float r[64];
    int g = blockIdx.x;
    r[threadIdx.x] = g_readout[(size_t)g * 64 + threadIdx.x];
    __syncthreads();
    int c = threadIdx.x;
    if (c < 40) {
        float acc = b[c];
#pragma unroll
        for (int k = 0; k < 64; k++) acc = fmaf(r[k], __ldg(&W[k * 40 + c]), acc);
        out[(size_t)g * 40 + c] = acc;
    }
}

// ---------------- launch ----------------
extern "C" void kernel_launch(void* const* d_in, const int* in_sizes, int n_in,
                              void* d_out, int out_size) {
    const float* x      = (const float*)d_in[0];
    const void*  eidx   = d_in[1];
    const void*  batch  = d_in[2];
    const float* pre_w  = (const float*)d_in[3];
    const float* pre_b  = (const float*)d_in[4];
    const float* c1_w   = (const float*)d_in[5];
    const float* c1_b   = (const float*)d_in[6];
    const float* n1_g   = (const float*)d_in[7];
    const float* n1_b   = (const float*)d_in[8];
    const float* c2_w   = (const float*)d_in[9];
    const float* c2_b   = (const float*)d_in[10];
    const float* n2_g   = (const float*)d_in[11];
    const float* n2_b   = (const float*)d_in[12];
    const float* post_w = (const float*)d_in[13];
    const float* post_b = (const float*)d_in[14];

    int N = in_sizes[0] / 128;
    int E = in_sizes[1] / 2;
    int G = out_size / 40;

    float* p_readout;
    __half *p_hws, *p_h1;
    int *p_cnt, *p_flag;
    cudaGetSymbolAddress((void**)&p_hws,     g_hws);
    cudaGetSymbolAddress((void**)&p_h1,      g_h1);
    cudaGetSymbolAddress((void**)&p_cnt,     g_cnt);
    cudaGetSymbolAddress((void**)&p_flag,    g_scanflag);
    cudaGetSymbolAddress((void**)&p_readout, g_readout);

    static cudaStream_t s1 = nullptr, s2 = nullptr;
    static cudaEvent_t evFork = nullptr, evHist = nullptr, evG1 = nullptr, evCsr = nullptr;
    if (!s1) {
        cudaStreamCreateWithFlags(&s1, cudaStreamNonBlocking);
        cudaStreamCreateWithFlags(&s2, cudaStreamNonBlocking);
        cudaEventCreateWithFlags(&evFork, cudaEventDisableTiming);
        cudaEventCreateWithFlags(&evHist, cudaEventDisableTiming);
        cudaEventCreateWithFlags(&evG1,   cudaEventDisableTiming);
        cudaEventCreateWithFlags(&evCsr,  cudaEventDisableTiming);
        cudaFuncSetAttribute(k_gemm0, cudaFuncAttributeMaxDynamicSharedMemorySize, 65536);
    }

    cudaEventRecord(evFork, 0);
    cudaStreamWaitEvent(s1, evFork, 0);
    cudaStreamWaitEvent(s2, evFork, 0);

    // --- s2: memsets + CSR build ---
    cudaMemsetAsync(p_cnt, 0, (size_t)N * 4, s2);
    cudaMemsetAsync(p_flag, 0, 128 * 4, s2);
    cudaMemsetAsync(p_readout, 0, (size_t)G * 64 * 4, s2);
    k_hist<<<(E + 1023) / 1024, 256, 0, s2>>>(eidx, E, (long long)N);
    cudaEventRecord(evHist, s2);
    k_scan<<<(N + 1023) / 1024, 256, 0, s2>>>(N);
    k_fill<<<(E + 1023) / 1024, 256, 0, s2>>>(eidx, E, (long long)N);
    cudaEventRecord(evCsr, s2);

    // --- s1: fused pre-MLP + layer-1 GEMM (needs only hist counts) ---
    cudaStreamWaitEvent(s1, evHist, 0);
    k_gemm0<<<(N + 127) / 128, 256, 64512, s1>>>(x, pre_w, pre_b, c1_w, p_cnt, p_hws, N);
    cudaEventRecord(evG1, s1);

    // --- join ---
    cudaStreamWaitEvent(0, evG1, 0);
    cudaStreamWaitEvent(0, evCsr, 0);

    // layer 1 gather -> h1 (fp16)
    k_gather<<<((size_t)N * 8 + 255) / 256, 256>>>(c1_b, n1_g, n1_b, p_h1, N, 0, nullptr);

    // layer 2
    k_gemm_h<<<(N + 127) / 128, 256>>>(p_h1, c2_w, p_cnt, p_hws, N);
    k_gather<<<((size_t)N * 8 + 255) / 256, 256>>>(c2_b, n2_g, n2_b, nullptr, N, 1, batch);

    // post
    k_post<<<G, 64>>>(post_w, post_b, (float*)d_out, G);
}